// round 10
// baseline (speedup 1.0000x reference)
#include <cuda_runtime.h>
#include <cuda_fp16.h>
#include <cstdint>
#include <cmath>

// ============================================================================
// Problem constants
// ============================================================================
#define BATCH  16384
#define DIN    1024
#define DFEAT  4096
#define DEG    3

// Tiling: each CTA computes 256(m) x 64(n) as TWO M=128 dispatch groups that
// share B tiles. A operand lives in TMEM (TS-mode); A-convert is software-
// pipelined one K-iteration ahead of the MMA that consumes it.
// Grid is 1-D with an L2-residency rasterization: bands of NBAND n-tiles,
// all m-tiles within a band before the next band.
#define TM 256
#define TN 64
#define BK 32          // 32 halves; combined row = [hi 64B | lo 64B] = 128B (SW128)
#define NK (DIN / BK)  // 32 K-chunks
#define STAGES 3

#define NTILES_N (DFEAT / TN)    // 64
#define NTILES_M (BATCH / TM)    // 64
#define NBAND    16              // n-tiles per band; wave ~ 16n x 9m => ~22MB hot set

#define KTILE_AH 16384                      // one M-half: 128 rows x 128B
#define KTILE_A  (2 * KTILE_AH)             // 32768
#define KTILE_B  8192                       // 64 rows x 128B
#define STAGE_BYTES (KTILE_A + DEG * KTILE_B)   // 57344
#define SMEM_TILES  1024
#define SMEM_TOTAL  (SMEM_TILES + STAGES * STAGE_BYTES)   // 173056

// SMEM control offsets
#define OFF_TMEM     0
#define OFF_EMPTY(s) (16 + 8 * (s))
#define OFF_MMADONE  48

// TMEM layout: 6 fp32 accumulators (d, mh) x 64 cols = 0..383;
// two A slots of 64 cols each at 384/448 (per slot: mh*32 + {0:hi16, 16:lo16})
#define TMEM_ACC(d, mh) (((d) * 2 + (mh)) * 64)
#define TMEM_ASLOT(i)   (384 + (i) * 64)
#define TMEM_COLS 512

// idesc kind::f16: dtype=F32 (bit4), atype/btype=F16 (0),
// N>>3 at [17:22], M>>4 at [24:28]  (per-dispatch M=128, N=64)
static constexpr uint32_t MMA_IDESC =
    (1u << 4) | ((TN / 8) << 17) | ((128 / 16) << 24);

// ============================================================================
// Scratch (device globals -- sanctioned, no runtime allocation)
// ============================================================================
__device__ __half g_xh[(size_t)BATCH * DIN];
__device__ __half g_xl[(size_t)BATCH * DIN];
__device__ __half g_wh[(size_t)DEG * DFEAT * DIN];   // [d][o][i]
__device__ __half g_wl[(size_t)DEG * DFEAT * DIN];

// ============================================================================
// Helpers legal on ALL targets
// ============================================================================
__device__ __forceinline__ uint32_t smem_u32(const void* p) {
    uint32_t a;
    asm("{ .reg .u64 t; cvta.to.shared.u64 t, %1; cvt.u32.u64 %0, t; }"
        : "=r"(a) : "l"(p));
    return a;
}

#define CP_ASYNC16(dst, src) \
    asm volatile("cp.async.cg.shared.global [%0], [%1], 16;" \
                 :: "r"(dst), "l"(src) : "memory")
#define CP_COMMIT() asm volatile("cp.async.commit_group;" ::: "memory")
#define CP_WAIT(n)  asm volatile("cp.async.wait_group %0;" :: "n"(n) : "memory")

#define SWZ128(off) ((off) ^ (((off) >> 3) & 0x70))

// L2-residency rasterization: band of NBAND n-tiles, m-major inside the band.
__device__ __forceinline__ void tile_coords(int bid, int* n0, int* m0) {
    int band = bid / (NBAND * NTILES_M);
    int r    = bid % (NBAND * NTILES_M);
    int nb   = band * NBAND + (r % NBAND);
    int mb   = r / NBAND;
    *n0 = nb * TN;
    *m0 = mb * TM;
}

// ============================================================================
// Pre-pass 1: x -> (hi, lo) fp16 pair, scaled by exp(-log_lengthscale)
// ============================================================================
__global__ void convert_x_kernel(const float* __restrict__ x,
                                 const float* __restrict__ lls) {
    float s = expf(-lls[0]);
    size_t idx = ((size_t)blockIdx.x * blockDim.x + threadIdx.x) * 4;
    float4 v = *reinterpret_cast<const float4*>(x + idx);
    float f[4] = {v.x * s, v.y * s, v.z * s, v.w * s};
    __half hi[4], lo[4];
    #pragma unroll
    for (int j = 0; j < 4; j++) {
        hi[j] = __float2half_rn(f[j]);
        lo[j] = __float2half_rn(f[j] - __half2float(hi[j]));
    }
    *reinterpret_cast<uint2*>(g_xh + idx) = *reinterpret_cast<uint2*>(hi);
    *reinterpret_cast<uint2*>(g_xl + idx) = *reinterpret_cast<uint2*>(lo);
}

// ============================================================================
// Pre-pass 2: W [d][i][o] fp32 -> transposed (hi, lo) fp16 pairs [d][o][i]
// ============================================================================
__global__ void convert_w_kernel(const float* __restrict__ W) {
    __shared__ float tile[32][33];
    int d  = blockIdx.z;
    int o0 = blockIdx.x * 32;
    int i0 = blockIdx.y * 32;
    int tx = threadIdx.x, ty = threadIdx.y;
    tile[ty][tx] = W[((size_t)d * DIN + (i0 + ty)) * DFEAT + (o0 + tx)];
    __syncthreads();
    float f = tile[tx][ty];
    __half hi = __float2half_rn(f);
    __half lo = __float2half_rn(f - __half2float(hi));
    size_t o = ((size_t)d * DFEAT + (o0 + ty)) * DIN + (i0 + tx);
    g_wh[o] = hi;
    g_wl[o] = lo;
}

// ============================================================================
// Main fused kernel: 3-term fp16-split GEMMs, 256x64 per CTA, TS-mode (A in
// TMEM, convert pipelined one iteration ahead), six fp32 TMEM accumulators,
// fused product epilogue. 1-D grid + band rasterization for L2 residency.
// ============================================================================
__global__ void __launch_bounds__(128, 1)
sketch_kernel(float* __restrict__ out, const float* __restrict__ lv) {
#if defined(__CUDA_ARCH_FEAT_SM103_ALL) || defined(__CUDA_ARCH_FEAT_SM100_ALL)
    // ------------------------------------------------------------------
    // tcgen05 TS path
    // ------------------------------------------------------------------
    extern __shared__ char smem[];
    uint32_t sb = smem_u32(smem);
    int tid = threadIdx.x;
    int wid = tid >> 5, lid = tid & 31;
    int n0, m0;
    tile_coords((int)blockIdx.x, &n0, &m0);
    uint32_t warp_off = ((uint32_t)wid) << 21;   // TMEM lane-partition select

    if (wid == 0) {
        asm volatile("tcgen05.alloc.cta_group::1.sync.aligned.shared::cta.b32 [%0], %1;"
                     :: "r"(sb + OFF_TMEM), "r"((uint32_t)TMEM_COLS) : "memory");
        asm volatile("tcgen05.relinquish_alloc_permit.cta_group::1.sync.aligned;");
    }
    if (tid == 0) {
        #pragma unroll
        for (int s = 0; s < STAGES; s++) {
            asm volatile("mbarrier.init.shared.b64 [%0], %1;"
                         :: "r"(sb + OFF_EMPTY(s)), "r"(1) : "memory");
        }
        asm volatile("mbarrier.init.shared.b64 [%0], %1;"
                     :: "r"(sb + OFF_MMADONE), "r"(1) : "memory");
    }
    __syncthreads();
    uint32_t tmem;
    asm volatile("ld.shared.b32 %0, [%1];" : "=r"(tmem) : "r"(sb + OFF_TMEM));

    #define MBAR_WAIT(addr, parity) do {                                           \
        uint32_t _m = (addr), _p = (parity), _d;                                   \
        asm volatile("{ .reg .pred p; "                                            \
            "mbarrier.try_wait.parity.acquire.cta.shared::cta.b64 p, [%1], %2; "   \
            "selp.b32 %0, 1, 0, p; }" : "=r"(_d) : "r"(_m), "r"(_p) : "memory");   \
        if (!_d) {                                                                 \
            asm volatile("{ .reg .pred P; L_%=: "                                  \
                "mbarrier.try_wait.parity.acquire.cta.shared::cta.b64 P, [%0], %1, 0x989680; " \
                "@P bra.uni D_%=; bra.uni L_%=; D_%=: }"                           \
                :: "r"(_m), "r"(_p) : "memory");                                   \
        }                                                                          \
    } while (0)

    #define TC_ST_X16(taddr, r)                                                    \
        asm volatile("tcgen05.st.sync.aligned.32x32b.x16.b32 [%0], "               \
            "{%1,%2,%3,%4,%5,%6,%7,%8,%9,%10,%11,%12,%13,%14,%15,%16};"            \
            :: "r"(taddr),                                                         \
               "r"((r)[0]),  "r"((r)[1]),  "r"((r)[2]),  "r"((r)[3]),              \
               "r"((r)[4]),  "r"((r)[5]),  "r"((r)[6]),  "r"((r)[7]),              \
               "r"((r)[8]),  "r"((r)[9]),  "r"((r)[10]), "r"((r)[11]),             \
               "r"((r)[12]), "r"((r)[13]), "r"((r)[14]), "r"((r)[15]) : "memory")

    // Stage loader: A 256 rows + 3 B tiles (64 rows); [hi 64B | lo 64B] rows.
    auto load_stage = [&](int s, int kt) {
        uint32_t base = sb + SMEM_TILES + s * STAGE_BYTES;
        const __half* ah = g_xh + (size_t)m0 * DIN + kt * BK;
        const __half* al = g_xl + (size_t)m0 * DIN + kt * BK;
        #pragma unroll
        for (int c = tid; c < 2048; c += 128) {
            int row = c >> 3, ch = c & 7;   // row 0..255
            uint32_t off = (uint32_t)(row << 7) | (uint32_t)(ch << 4);
            const __half* src = (ch < 4) ? (ah + (size_t)row * DIN + ch * 8)
                                         : (al + (size_t)row * DIN + (ch - 4) * 8);
            CP_ASYNC16(base + SWZ128(off), src);
        }
        #pragma unroll
        for (int d = 0; d < DEG; d++) {
            const __half* bh = g_wh + ((size_t)d * DFEAT + n0) * DIN + kt * BK;
            const __half* bl = g_wl + ((size_t)d * DFEAT + n0) * DIN + kt * BK;
            uint32_t tb = base + KTILE_A + d * KTILE_B;
            #pragma unroll
            for (int c = tid; c < 512; c += 128) {
                int row = c >> 3, ch = c & 7;   // row 0..63
                uint32_t off = (uint32_t)(row << 7) | (uint32_t)(ch << 4);
                const __half* src = (ch < 4) ? (bh + (size_t)row * DIN + ch * 8)
                                             : (bl + (size_t)row * DIN + (ch - 4) * 8);
                CP_ASYNC16(tb + SWZ128(off), src);
            }
        }
    };

    // A convert: stage (kt%STAGES) SMEM -> regs -> TMEM slot (kt&1).
    auto conv_A = [&](int kt) {
        uint32_t abase = sb + SMEM_TILES + (kt % STAGES) * STAGE_BYTES;
        uint32_t slot = tmem + TMEM_ASLOT(kt & 1);
        #pragma unroll
        for (int mh = 0; mh < 2; mh++) {
            uint32_t row = (uint32_t)(mh * 128 + tid);
            uint32_t rh[16], rl[16];
            #pragma unroll
            for (int c2 = 0; c2 < 4; c2++) {   // hi: bytes 0..63
                uint32_t addr = abase + SWZ128((row << 7) | (uint32_t)(c2 << 4));
                asm volatile("ld.shared.v4.b32 {%0,%1,%2,%3}, [%4];"
                    : "=r"(rh[c2*4]), "=r"(rh[c2*4+1]), "=r"(rh[c2*4+2]), "=r"(rh[c2*4+3])
                    : "r"(addr));
            }
            #pragma unroll
            for (int c2 = 0; c2 < 4; c2++) {   // lo: bytes 64..127
                uint32_t addr = abase + SWZ128((row << 7) | (uint32_t)((c2 + 4) << 4));
                asm volatile("ld.shared.v4.b32 {%0,%1,%2,%3}, [%4];"
                    : "=r"(rl[c2*4]), "=r"(rl[c2*4+1]), "=r"(rl[c2*4+2]), "=r"(rl[c2*4+3])
                    : "r"(addr));
            }
            TC_ST_X16(slot + mh * 32 + warp_off, rh);
            TC_ST_X16(slot + mh * 32 + 16 + warp_off, rl);
        }
        asm volatile("tcgen05.wait::st.sync.aligned;" ::: "memory");
        asm volatile("tcgen05.fence::before_thread_sync;" ::: "memory");
        __syncthreads();
    };

    // K-major SW128 descriptor: LBO=1 (16B), SBO=64 (1024B), version 1
    constexpr uint64_t DESC_BASE =
        (uint64_t(2) << 61) | (uint64_t(1) << 46) | (uint64_t(64) << 32) | (uint64_t(1) << 16);

    // Prologue: 2 chunks in flight, convert A chunk 0
    load_stage(0, 0);
    CP_COMMIT();
    load_stage(1, 1);
    CP_COMMIT();
    CP_WAIT(1);
    __syncthreads();   // stage 0 (A + B) visible
    conv_A(0);

    for (int kt = 0; kt < NK; kt++) {
        int s = kt % STAGES;

        // 1. Issue MMA(kt): A slot (kt&1) converted, stage s B resident.
        if (wid == 0) {
            uint32_t is_elect;
            asm volatile("{ .reg .pred p; elect.sync _|p, 0xFFFFFFFF; selp.b32 %0, 1, 0, p; }"
                         : "=r"(is_elect));
            if (is_elect) {
                asm volatile("fence.proxy.async.shared::cta;" ::: "memory");
                asm volatile("tcgen05.fence::after_thread_sync;" ::: "memory");
                uint32_t stage_base = sb + SMEM_TILES + s * STAGE_BYTES;
                uint32_t aslot = tmem + TMEM_ASLOT(kt & 1);
                #pragma unroll
                for (int d = 0; d < DEG; d++) {
                    uint32_t bb = stage_base + KTILE_A + d * KTILE_B;
                    uint64_t bd = DESC_BASE | ((uint64_t)(bb >> 4) & 0x3FFF);
                    #pragma unroll
                    for (int mh = 0; mh < 2; mh++) {
                        uint32_t acc_t = tmem + TMEM_ACC(d, mh);
                        uint32_t at = aslot + mh * 32;
                        #pragma unroll
                        for (int ks = 0; ks < 2; ks++) {
                            uint32_t acc0 = (kt > 0 || ks > 0) ? 1u : 0u;
                            // hi * hi
                            asm volatile(
                                "{ .reg .pred p; setp.ne.u32 p, %5, 0;"
                                "tcgen05.mma.cta_group::1.kind::f16 [%0], [%1], %2, %3, {%4, %4, %4, %4}, p; }"
                                :: "r"(acc_t), "r"(at + ks * 8),
                                   "l"(bd + ks * 2), "r"(MMA_IDESC), "r"(0u), "r"(acc0)
                                : "memory");
                            // lo * hi  (A lo cols at +16)
                            asm volatile(
                                "{ .reg .pred p; setp.ne.u32 p, %5, 0;"
                                "tcgen05.mma.cta_group::1.kind::f16 [%0], [%1], %2, %3, {%4, %4, %4, %4}, p; }"
                                :: "r"(acc_t), "r"(at + 16 + ks * 8),
                                   "l"(bd + ks * 2), "r"(MMA_IDESC), "r"(0u), "r"(1u)
                                : "memory");
                            // hi * lo  (B lo half at +64B = +4 desc units)
                            asm volatile(
                                "{ .reg .pred p; setp.ne.u32 p, %5, 0;"
                                "tcgen05.mma.cta_group::1.kind::f16 [%0], [%1], %2, %3, {%4, %4, %4, %4}, p; }"
                                :: "r"(acc_t), "r"(at + ks * 8),
                                   "l"(bd + 4 + ks * 2), "r"(MMA_IDESC), "r"(0u), "r"(1u)
                                : "memory");
                        }
                    }
                }
                if (kt == NK - 1)
                    asm volatile("tcgen05.commit.cta_group::1.mbarrier::arrive::one.shared::cluster.b64 [%0];"
                                 :: "r"(sb + OFF_MMADONE) : "memory");
                else
                    asm volatile("tcgen05.commit.cta_group::1.mbarrier::arrive::one.shared::cluster.b64 [%0];"
                                 :: "r"(sb + OFF_EMPTY(s)) : "memory");
            }
        }

        // 2. Gate on MMA(kt-1) done: frees SMEM stage (kt+2)%3 for reload AND
        //    TMEM A slot (kt+1)&1 for the next convert.
        if (kt >= 1) {
            MBAR_WAIT(sb + OFF_EMPTY((kt - 1) % STAGES), (((kt - 1) / STAGES) & 1));
        }

        // 3. Prefetch stage kt+2 (empty commit when out of range keeps the
        //    cp.async group bookkeeping uniform for the CP_WAIT below).
        if (kt + 2 < NK) load_stage((kt + 2) % STAGES, kt + 2);
        CP_COMMIT();

        // 4. Wait for stage kt+1 data, then convert its A into the free slot.
        //    Overlaps with the tensor unit executing MMA(kt).
        if (kt + 1 < NK) {
            CP_WAIT(1);
            __syncthreads();   // stage kt+1 tiles visible to all threads
            conv_A(kt + 1);
        }
    }

    // Epilogue: wait all MMAs, product of 3 degrees per m-half, scale, store.
    MBAR_WAIT(sb + OFF_MMADONE, 0);
    asm volatile("tcgen05.fence::after_thread_sync;" ::: "memory");

    float scale = 0.015625f * expf(0.5f * lv[0]);   // 1/sqrt(4096) * exp(lv/2)

    #define TC_LD_X32(r, tmem_addr) \
        asm volatile( \
            "tcgen05.ld.sync.aligned.32x32b.x32.b32 " \
            "{%0, %1, %2, %3, %4, %5, %6, %7, " \
            " %8, %9, %10, %11, %12, %13, %14, %15, " \
            " %16, %17, %18, %19, %20, %21, %22, %23, " \
            " %24, %25, %26, %27, %28, %29, %30, %31}, [%32];" \
            : "=r"((r)[0]),  "=r"((r)[1]),  "=r"((r)[2]),  "=r"((r)[3]), \
              "=r"((r)[4]),  "=r"((r)[5]),  "=r"((r)[6]),  "=r"((r)[7]), \
              "=r"((r)[8]),  "=r"((r)[9]),  "=r"((r)[10]), "=r"((r)[11]), \
              "=r"((r)[12]), "=r"((r)[13]), "=r"((r)[14]), "=r"((r)[15]), \
              "=r"((r)[16]), "=r"((r)[17]), "=r"((r)[18]), "=r"((r)[19]), \
              "=r"((r)[20]), "=r"((r)[21]), "=r"((r)[22]), "=r"((r)[23]), \
              "=r"((r)[24]), "=r"((r)[25]), "=r"((r)[26]), "=r"((r)[27]), \
              "=r"((r)[28]), "=r"((r)[29]), "=r"((r)[30]), "=r"((r)[31]) \
            : "r"(tmem_addr))

    #pragma unroll
    for (int mh = 0; mh < 2; mh++) {
        float* orow = out + (size_t)(m0 + mh * 128 + wid * 32 + lid) * DFEAT + n0;
        #pragma unroll
        for (int c = 0; c < TN / 32; c++) {
            uint32_t r0[32], r1[32], r2[32];
            TC_LD_X32(r0, tmem + TMEM_ACC(0, mh) + c * 32);
            TC_LD_X32(r1, tmem + TMEM_ACC(1, mh) + c * 32);
            TC_LD_X32(r2, tmem + TMEM_ACC(2, mh) + c * 32);
            asm volatile("tcgen05.wait::ld.sync.aligned;" ::: "memory");
            float f[32];
            #pragma unroll
            for (int j = 0; j < 32; j++) {
                f[j] = __uint_as_float(r0[j]) * __uint_as_float(r1[j]) *
                       __uint_as_float(r2[j]) * scale;
            }
            #pragma unroll
            for (int q = 0; q < 8; q++) {
                float4 v = make_float4(f[q * 4], f[q * 4 + 1], f[q * 4 + 2], f[q * 4 + 3]);
                *reinterpret_cast<float4*>(orow + c * 32 + q * 4) = v;
            }
        }
    }

    asm volatile("tcgen05.fence::before_thread_sync;" ::: "memory");
    __syncthreads();
    if (wid == 0) {
        asm volatile("tcgen05.dealloc.cta_group::1.sync.aligned.b32 %0, %1;"
                     :: "r"(tmem), "r"((uint32_t)TMEM_COLS));
    }
    #undef MBAR_WAIT
    #undef TC_ST_X16
    #undef TC_LD_X32

#else
    // ------------------------------------------------------------------
    // Fallback path (base sm_103): cp.async + ldmatrix + mma.sync, same
    // 3-term fp16 split. 4 passes (mh x 32-col n-slice); same band raster.
    // ------------------------------------------------------------------
    extern __shared__ char smem[];
    uint32_t sb = smem_u32(smem);
    int tid  = threadIdx.x;
    int wid  = tid >> 5;
    int lane = tid & 31;
    int n0, m0;
    tile_coords((int)blockIdx.x, &n0, &m0);

    float scale = 0.015625f * expf(0.5f * lv[0]);

    auto load_stage_fb = [&](int s, int kt, int mh, int p) {
        uint32_t base = sb + SMEM_TILES + s * STAGE_BYTES;
        int ma = m0 + mh * 128;
        const __half* ah = g_xh + (size_t)ma * DIN + kt * BK;
        const __half* al = g_xl + (size_t)ma * DIN + kt * BK;
        #pragma unroll
        for (int c = tid; c < 1024; c += 128) {
            int row = c >> 3, ch = c & 7;
            uint32_t off = (uint32_t)(row << 7) | (uint32_t)(ch << 4);
            const __half* src = (ch < 4) ? (ah + (size_t)row * DIN + ch * 8)
                                         : (al + (size_t)row * DIN + (ch - 4) * 8);
            CP_ASYNC16(base + SWZ128(off), src);
        }
        #pragma unroll
        for (int d = 0; d < DEG; d++) {
            size_t brow = (size_t)d * DFEAT + n0 + 32 * p;
            const __half* bh = g_wh + brow * DIN + kt * BK;
            const __half* bl = g_wl + brow * DIN + kt * BK;
            uint32_t tb = base + KTILE_A + d * KTILE_B;
            #pragma unroll
            for (int j = 0; j < 2; j++) {
                int c = tid + 128 * j;
                int row = c >> 3, ch = c & 7;
                uint32_t off = (uint32_t)(row << 7) | (uint32_t)(ch << 4);
                const __half* src = (ch < 4) ? (bh + (size_t)row * DIN + ch * 8)
                                             : (bl + (size_t)row * DIN + (ch - 4) * 8);
                CP_ASYNC16(tb + SWZ128(off), src);
            }
        }
    };

    int lr = lane & 15;
    int lc = lane >> 4;

    for (int pass = 0; pass < 4; pass++) {
        int mh = pass >> 1, p = pass & 1;
        float acc[DEG][2][4][4];
        #pragma unroll
        for (int d = 0; d < DEG; d++)
            #pragma unroll
            for (int mt = 0; mt < 2; mt++)
                #pragma unroll
                for (int nt = 0; nt < 4; nt++)
                    #pragma unroll
                    for (int r = 0; r < 4; r++) acc[d][mt][nt][r] = 0.0f;

        #pragma unroll
        for (int s = 0; s < STAGES - 1; s++) {
            load_stage_fb(s, s, mh, p);
            CP_COMMIT();
        }

        for (int kt = 0; kt < NK; kt++) {
            CP_WAIT(STAGES - 2);
            __syncthreads();
            int s = kt % STAGES;
            uint32_t abase = sb + SMEM_TILES + s * STAGE_BYTES;

            #pragma unroll
            for (int ks = 0; ks < 2; ks++) {
                uint32_t a_hi[2][4], a_lo[2][4];
                #pragma unroll
                for (int mt = 0; mt < 2; mt++) {
                    uint32_t row = 32 * wid + 16 * mt + lr;
                    uint32_t byt = (uint32_t)(ks * 32 + lc * 16);
                    uint32_t addr_h = abase + SWZ128((row << 7) | byt);
                    uint32_t addr_l = abase + SWZ128((row << 7) | (64 + byt));
                    asm volatile(
                        "ldmatrix.sync.aligned.m8n8.x4.shared.b16 {%0,%1,%2,%3}, [%4];"
                        : "=r"(a_hi[mt][0]), "=r"(a_hi[mt][1]), "=r"(a_hi[mt][2]), "=r"(a_hi[mt][3])
                        : "r"(addr_h));
                    asm volatile(
                        "ldmatrix.sync.aligned.m8n8.x4.shared.b16 {%0,%1,%2,%3}, [%4];"
                        : "=r"(a_lo[mt][0]), "=r"(a_lo[mt][1]), "=r"(a_lo[mt][2]), "=r"(a_lo[mt][3])
                        : "r"(addr_l));
                }
                #pragma unroll
                for (int d = 0; d < DEG; d++) {
                    uint32_t bbase = abase + KTILE_A + d * KTILE_B;
                    uint32_t b_hi[2][4], b_lo[2][4];
                    #pragma unroll
                    for (int h = 0; h < 2; h++) {
                        uint32_t row = 16 * h + lr;
                        uint32_t byt = (uint32_t)(ks * 32 + lc * 16);
                        uint32_t addr_h = bbase + SWZ128((row << 7) | byt);
                        uint32_t addr_l = bbase + SWZ128((row << 7) | (64 + byt));
                        asm volatile(
                            "ldmatrix.sync.aligned.m8n8.x4.shared.b16 {%0,%1,%2,%3}, [%4];"
                            : "=r"(b_hi[h][0]), "=r"(b_hi[h][1]), "=r"(b_hi[h][2]), "=r"(b_hi[h][3])
                            : "r"(addr_h));
                        asm volatile(
                            "ldmatrix.sync.aligned.m8n8.x4.shared.b16 {%0,%1,%2,%3}, [%4];"
                            : "=r"(b_lo[h][0]), "=r"(b_lo[h][1]), "=r"(b_lo[h][2]), "=r"(b_lo[h][3])
                            : "r"(addr_l));
                    }
                    #pragma unroll
                    for (int mt = 0; mt < 2; mt++) {
                        #pragma unroll
                        for (int nt = 0; nt < 4; nt++) {
                            int h = nt >> 1, lo = nt & 1;
                            float* c = acc[d][mt][nt];
                            asm volatile(
                                "mma.sync.aligned.m16n8k16.row.col.f32.f16.f16.f32 "
                                "{%0,%1,%2,%3}, {%4,%5,%6,%7}, {%8,%9}, {%0,%1,%2,%3};"
                                : "+f"(c[0]), "+f"(c[1]), "+f"(c[2]), "+f"(c[3])
                                : "r"(a_hi[mt][0]), "r"(a_hi[mt][1]), "r"(a_hi[mt][2]), "r"(a_hi[mt][3]),
                                  "r"(b_hi[h][lo]), "r"(b_hi[h][lo + 2]));
                            asm volatile(
                                "mma.sync.aligned.m16n8k16.row.col.f32.f16.f16.f32 "
                                "{%0,%1,%2,%3}, {%4,%5,%6,%7}, {%8,%9}, {%0,%1,%2,%3};"
                                : "+f"(c[0]), "+f"(c[1]), "+f"(c[2]), "+f"(c[3])
                                : "r"(a_lo[mt][0]), "r"(a_lo[mt][1]), "r"(a_lo[mt][2]), "r"(a_lo[mt][3]),
                                  "r"(b_hi[h][lo]), "r"(b_hi[h][lo + 2]));
                            asm volatile(
                                "mma.sync.aligned.m16n8k16.row.col.f32.f16.f16.f32 "
                                "{%0,%1,%2,%3}, {%4,%5,%6,%7}, {%8,%9}, {%0,%1,%2,%3};"
                                : "+f"(c[0]), "+f"(c[1]), "+f"(c[2]), "+f"(c[3])
                                : "r"(a_hi[mt][0]), "r"(a_hi[mt][1]), "r"(a_hi[mt][2]), "r"(a_hi[mt][3]),
                                  "r"(b_lo[h][lo]), "r"(b_lo[h][lo + 2]));
                        }
                    }
                }
            }
            __syncthreads();
            int nk = kt + STAGES - 1;
            if (nk < NK) load_stage_fb(nk % STAGES, nk, mh, p);
            CP_COMMIT();
        }
        CP_WAIT(0);
        __syncthreads();

        int g = lane >> 2, t = lane & 3;
        #pragma unroll
        for (int mt = 0; mt < 2; mt++) {
            #pragma unroll
            for (int nt = 0; nt < 4; nt++) {
                int row = m0 + mh * 128 + 32 * wid + 16 * mt + g;
                int col = n0 + 32 * p + 8 * nt + 2 * t;
                float p0 = acc[0][mt][nt][0] * acc[1][mt][nt][0] * acc[2][mt][nt][0] * scale;
                float p1 = acc[0][mt][nt][1] * acc[1][mt][nt][1] * acc[2][mt][nt][1] * scale;
                float p2 = acc[0][mt][nt][2] * acc[1][mt][nt][2] * acc[2][mt][nt][2] * scale;
                float p3 = acc[0][mt][nt][3] * acc[1][mt][nt][3] * acc[2][mt][nt][3] * scale;
                *reinterpret_cast<float2*>(out + (size_t)row * DFEAT + col) =
                    make_float2(p0, p1);
                *reinterpret_cast<float2*>(out + (size_t)(row + 8) * DFEAT + col) =
                    make_float2(p2, p3);
            }
        }
    }
#endif
}

// ============================================================================
// Launch
// ============================================================================
extern "C" void kernel_launch(void* const* d_in, const int* in_sizes, int n_in,
                              void* d_out, int out_size) {
    const float* x   = (const float*)d_in[0];
    const float* W   = (const float*)d_in[1];
    const float* lls = (const float*)d_in[2];
    const float* lv  = (const float*)d_in[3];
    float* out = (float*)d_out;

    convert_x_kernel<<<(BATCH * (size_t)DIN) / (4 * 256), 256>>>(x, lls);
    convert_w_kernel<<<dim3(DFEAT / 32, DIN / 32, DEG), dim3(32, 32)>>>(W);

    cudaFuncSetAttribute(sketch_kernel,
                         cudaFuncAttributeMaxDynamicSharedMemorySize, SMEM_TOTAL);
    // 1-D grid with band rasterization (see tile_coords)
    sketch_kernel<<<NTILES_N * NTILES_M, 128, SMEM_TOTAL>>>(out, lv);
}

// round 11
// speedup vs baseline: 1.0631x; 1.0631x over previous
#include <cuda_runtime.h>
#include <cuda_fp16.h>
#include <cstdint>
#include <cmath>

// ============================================================================
// Problem constants
// ============================================================================
#define BATCH  16384
#define DIN    1024
#define DFEAT  4096
#define DEG    3

// Tiling: 128(m) x 128(n) per CTA, TS-mode (A in TMEM). N=128 dispatches halve
// the tcgen05 dispatch count vs N=64 (dispatch-rate bound at ~64-70 cyc each).
#define TM 128
#define TN 128
#define BK 32          // 32 halves; combined row = [hi 64B | lo 64B] = 128B (SW128)
#define NK (DIN / BK)  // 32 K-chunks
#define STAGES 3

#define NTILES_N (DFEAT / TN)    // 32
#define NTILES_M (BATCH / TM)    // 128
#define NBAND    8               // n-tiles per band (L2 residency raster)

#define KTILE_A  16384                      // 128 rows x 128B
#define KTILE_B  16384                      // 128 rows x 128B
#define STAGE_BYTES (KTILE_A + DEG * KTILE_B)   // 65536
#define SMEM_TILES  1024
#define SMEM_TOTAL  (SMEM_TILES + STAGES * STAGE_BYTES)   // 197632

// SMEM control offsets
#define OFF_TMEM     0
#define OFF_EMPTY(s) (16 + 8 * (s))
#define OFF_MMADONE  48

// TMEM layout: 3 fp32 accumulators x 128 cols = 0..383;
// two A slots of 32 cols each at 384/416 (per slot: {0:hi16, 16:lo16})
#define TMEM_ACC(d)   ((d) * 128)
#define TMEM_ASLOT(i) (384 + (i) * 32)
#define TMEM_COLS 512

// idesc kind::f16: dtype=F32 (bit4), atype/btype=F16 (0),
// N>>3 at [17:22], M>>4 at [24:28]  (M=128, N=128)
static constexpr uint32_t MMA_IDESC =
    (1u << 4) | ((TN / 8) << 17) | ((TM / 16) << 24);

// ============================================================================
// Scratch (device globals -- sanctioned, no runtime allocation)
// ============================================================================
__device__ __half g_xh[(size_t)BATCH * DIN];
__device__ __half g_xl[(size_t)BATCH * DIN];
__device__ __half g_wh[(size_t)DEG * DFEAT * DIN];   // [d][o][i]
__device__ __half g_wl[(size_t)DEG * DFEAT * DIN];
__device__ float  g_scale;                            // 1/sqrt(F) * exp(lv/2)

// ============================================================================
// Helpers legal on ALL targets
// ============================================================================
__device__ __forceinline__ uint32_t smem_u32(const void* p) {
    uint32_t a;
    asm("{ .reg .u64 t; cvta.to.shared.u64 t, %1; cvt.u32.u64 %0, t; }"
        : "=r"(a) : "l"(p));
    return a;
}

#define CP_ASYNC16(dst, src) \
    asm volatile("cp.async.cg.shared.global [%0], [%1], 16;" \
                 :: "r"(dst), "l"(src) : "memory")
#define CP_COMMIT() asm volatile("cp.async.commit_group;" ::: "memory")
#define CP_WAIT(n)  asm volatile("cp.async.wait_group %0;" :: "n"(n) : "memory")

#define SWZ128(off) ((off) ^ (((off) >> 3) & 0x70))

// L2-residency rasterization: band of NBAND n-tiles, m-major inside the band.
__device__ __forceinline__ void tile_coords(int bid, int* n0, int* m0) {
    int band = bid / (NBAND * NTILES_M);
    int r    = bid % (NBAND * NTILES_M);
    int nb   = band * NBAND + (r % NBAND);
    int mb   = r / NBAND;
    *n0 = nb * TN;
    *m0 = mb * TM;
}

// ============================================================================
// Pre-pass 1: x -> (hi, lo) fp16 pair, scaled by exp(-log_lengthscale)
// ============================================================================
__global__ void convert_x_kernel(const float* __restrict__ x,
                                 const float* __restrict__ lls) {
    float s = expf(-lls[0]);
    size_t idx = ((size_t)blockIdx.x * blockDim.x + threadIdx.x) * 4;
    float4 v = *reinterpret_cast<const float4*>(x + idx);
    float f[4] = {v.x * s, v.y * s, v.z * s, v.w * s};
    __half hi[4], lo[4];
    #pragma unroll
    for (int j = 0; j < 4; j++) {
        hi[j] = __float2half_rn(f[j]);
        lo[j] = __float2half_rn(f[j] - __half2float(hi[j]));
    }
    *reinterpret_cast<uint2*>(g_xh + idx) = *reinterpret_cast<uint2*>(hi);
    *reinterpret_cast<uint2*>(g_xl + idx) = *reinterpret_cast<uint2*>(lo);
}

// ============================================================================
// Pre-pass 2: W [d][i][o] fp32 -> transposed (hi, lo) fp16 pairs [d][o][i]
// ============================================================================
__global__ void convert_w_kernel(const float* __restrict__ W) {
    __shared__ float tile[32][33];
    int d  = blockIdx.z;
    int o0 = blockIdx.x * 32;
    int i0 = blockIdx.y * 32;
    int tx = threadIdx.x, ty = threadIdx.y;
    tile[ty][tx] = W[((size_t)d * DIN + (i0 + ty)) * DFEAT + (o0 + tx)];
    __syncthreads();
    float f = tile[tx][ty];
    __half hi = __float2half_rn(f);
    __half lo = __float2half_rn(f - __half2float(hi));
    size_t o = ((size_t)d * DFEAT + (o0 + ty)) * DIN + (i0 + tx);
    g_wh[o] = hi;
    g_wl[o] = lo;
}

// ============================================================================
// Pre-pass 3: output scale (also aligns ncu's skip-5 window onto sketch)
// ============================================================================
__global__ void scale_kernel(const float* __restrict__ lv) {
    g_scale = 0.015625f * expf(0.5f * lv[0]);
}

// ============================================================================
// Main fused kernel: 3-term fp16-split GEMMs, 128x128 per CTA, TS-mode (A in
// TMEM, convert pipelined one iteration ahead), 3 fp32 TMEM accumulators,
// fused product epilogue. 1-D grid + band rasterization.
// ============================================================================
__global__ void __launch_bounds__(128, 1)
sketch_kernel(float* __restrict__ out) {
#if defined(__CUDA_ARCH_FEAT_SM103_ALL) || defined(__CUDA_ARCH_FEAT_SM100_ALL)
    // ------------------------------------------------------------------
    // tcgen05 TS path
    // ------------------------------------------------------------------
    extern __shared__ char smem[];
    uint32_t sb = smem_u32(smem);
    int tid = threadIdx.x;
    int wid = tid >> 5, lid = tid & 31;
    int n0, m0;
    tile_coords((int)blockIdx.x, &n0, &m0);
    uint32_t warp_off = ((uint32_t)wid) << 21;   // TMEM lane-partition select

    if (wid == 0) {
        asm volatile("tcgen05.alloc.cta_group::1.sync.aligned.shared::cta.b32 [%0], %1;"
                     :: "r"(sb + OFF_TMEM), "r"((uint32_t)TMEM_COLS) : "memory");
        asm volatile("tcgen05.relinquish_alloc_permit.cta_group::1.sync.aligned;");
    }
    if (tid == 0) {
        #pragma unroll
        for (int s = 0; s < STAGES; s++) {
            asm volatile("mbarrier.init.shared.b64 [%0], %1;"
                         :: "r"(sb + OFF_EMPTY(s)), "r"(1) : "memory");
        }
        asm volatile("mbarrier.init.shared.b64 [%0], %1;"
                     :: "r"(sb + OFF_MMADONE), "r"(1) : "memory");
    }
    __syncthreads();
    uint32_t tmem;
    asm volatile("ld.shared.b32 %0, [%1];" : "=r"(tmem) : "r"(sb + OFF_TMEM));

    #define MBAR_WAIT(addr, parity) do {                                           \
        uint32_t _m = (addr), _p = (parity), _d;                                   \
        asm volatile("{ .reg .pred p; "                                            \
            "mbarrier.try_wait.parity.acquire.cta.shared::cta.b64 p, [%1], %2; "   \
            "selp.b32 %0, 1, 0, p; }" : "=r"(_d) : "r"(_m), "r"(_p) : "memory");   \
        if (!_d) {                                                                 \
            asm volatile("{ .reg .pred P; L_%=: "                                  \
                "mbarrier.try_wait.parity.acquire.cta.shared::cta.b64 P, [%0], %1, 0x989680; " \
                "@P bra.uni D_%=; bra.uni L_%=; D_%=: }"                           \
                :: "r"(_m), "r"(_p) : "memory");                                   \
        }                                                                          \
    } while (0)

    #define TC_ST_X16(taddr, r)                                                    \
        asm volatile("tcgen05.st.sync.aligned.32x32b.x16.b32 [%0], "               \
            "{%1,%2,%3,%4,%5,%6,%7,%8,%9,%10,%11,%12,%13,%14,%15,%16};"            \
            :: "r"(taddr),                                                         \
               "r"((r)[0]),  "r"((r)[1]),  "r"((r)[2]),  "r"((r)[3]),              \
               "r"((r)[4]),  "r"((r)[5]),  "r"((r)[6]),  "r"((r)[7]),              \
               "r"((r)[8]),  "r"((r)[9]),  "r"((r)[10]), "r"((r)[11]),             \
               "r"((r)[12]), "r"((r)[13]), "r"((r)[14]), "r"((r)[15]) : "memory")

    // Stage loader: A 128 rows + 3 B tiles (128 rows); [hi 64B | lo 64B] rows.
    auto load_stage = [&](int s, int kt) {
        uint32_t base = sb + SMEM_TILES + s * STAGE_BYTES;
        const __half* ah = g_xh + (size_t)m0 * DIN + kt * BK;
        const __half* al = g_xl + (size_t)m0 * DIN + kt * BK;
        #pragma unroll
        for (int c = tid; c < 1024; c += 128) {
            int row = c >> 3, ch = c & 7;   // row 0..127
            uint32_t off = (uint32_t)(row << 7) | (uint32_t)(ch << 4);
            const __half* src = (ch < 4) ? (ah + (size_t)row * DIN + ch * 8)
                                         : (al + (size_t)row * DIN + (ch - 4) * 8);
            CP_ASYNC16(base + SWZ128(off), src);
        }
        #pragma unroll
        for (int d = 0; d < DEG; d++) {
            const __half* bh = g_wh + ((size_t)d * DFEAT + n0) * DIN + kt * BK;
            const __half* bl = g_wl + ((size_t)d * DFEAT + n0) * DIN + kt * BK;
            uint32_t tb = base + KTILE_A + d * KTILE_B;
            #pragma unroll
            for (int c = tid; c < 1024; c += 128) {
                int row = c >> 3, ch = c & 7;   // row 0..127
                uint32_t off = (uint32_t)(row << 7) | (uint32_t)(ch << 4);
                const __half* src = (ch < 4) ? (bh + (size_t)row * DIN + ch * 8)
                                             : (bl + (size_t)row * DIN + (ch - 4) * 8);
                CP_ASYNC16(tb + SWZ128(off), src);
            }
        }
    };

    // A convert: stage (kt%STAGES) SMEM -> regs -> TMEM slot (kt&1).
    auto conv_A = [&](int kt) {
        uint32_t abase = sb + SMEM_TILES + (kt % STAGES) * STAGE_BYTES;
        uint32_t slot = tmem + TMEM_ASLOT(kt & 1);
        uint32_t row = (uint32_t)tid;        // 0..127
        uint32_t rh[16], rl[16];
        #pragma unroll
        for (int c2 = 0; c2 < 4; c2++) {     // hi: bytes 0..63
            uint32_t addr = abase + SWZ128((row << 7) | (uint32_t)(c2 << 4));
            asm volatile("ld.shared.v4.b32 {%0,%1,%2,%3}, [%4];"
                : "=r"(rh[c2*4]), "=r"(rh[c2*4+1]), "=r"(rh[c2*4+2]), "=r"(rh[c2*4+3])
                : "r"(addr));
        }
        #pragma unroll
        for (int c2 = 0; c2 < 4; c2++) {     // lo: bytes 64..127
            uint32_t addr = abase + SWZ128((row << 7) | (uint32_t)((c2 + 4) << 4));
            asm volatile("ld.shared.v4.b32 {%0,%1,%2,%3}, [%4];"
                : "=r"(rl[c2*4]), "=r"(rl[c2*4+1]), "=r"(rl[c2*4+2]), "=r"(rl[c2*4+3])
                : "r"(addr));
        }
        TC_ST_X16(slot + warp_off, rh);
        TC_ST_X16(slot + 16 + warp_off, rl);
        asm volatile("tcgen05.wait::st.sync.aligned;" ::: "memory");
        asm volatile("tcgen05.fence::before_thread_sync;" ::: "memory");
        __syncthreads();
    };

    // K-major SW128 descriptor: LBO=1 (16B), SBO=64 (1024B), version 1
    constexpr uint64_t DESC_BASE =
        (uint64_t(2) << 61) | (uint64_t(1) << 46) | (uint64_t(64) << 32) | (uint64_t(1) << 16);

    // Prologue: 2 chunks in flight, convert A chunk 0
    load_stage(0, 0);
    CP_COMMIT();
    load_stage(1, 1);
    CP_COMMIT();
    CP_WAIT(1);
    __syncthreads();   // stage 0 (A + B) visible
    conv_A(0);

    for (int kt = 0; kt < NK; kt++) {
        int s = kt % STAGES;

        // 1. Issue MMA(kt): A slot (kt&1) converted, stage s B resident.
        if (wid == 0) {
            uint32_t is_elect;
            asm volatile("{ .reg .pred p; elect.sync _|p, 0xFFFFFFFF; selp.b32 %0, 1, 0, p; }"
                         : "=r"(is_elect));
            if (is_elect) {
                asm volatile("fence.proxy.async.shared::cta;" ::: "memory");
                asm volatile("tcgen05.fence::after_thread_sync;" ::: "memory");
                uint32_t stage_base = sb + SMEM_TILES + s * STAGE_BYTES;
                uint32_t aslot = tmem + TMEM_ASLOT(kt & 1);
                #pragma unroll
                for (int d = 0; d < DEG; d++) {
                    uint32_t bb = stage_base + KTILE_A + d * KTILE_B;
                    uint64_t bd = DESC_BASE | ((uint64_t)(bb >> 4) & 0x3FFF);
                    uint32_t acc_t = tmem + TMEM_ACC(d);
                    #pragma unroll
                    for (int ks = 0; ks < 2; ks++) {
                        uint32_t acc0 = (kt > 0 || ks > 0) ? 1u : 0u;
                        // hi * hi
                        asm volatile(
                            "{ .reg .pred p; setp.ne.u32 p, %5, 0;"
                            "tcgen05.mma.cta_group::1.kind::f16 [%0], [%1], %2, %3, {%4, %4, %4, %4}, p; }"
                            :: "r"(acc_t), "r"(aslot + ks * 8),
                               "l"(bd + ks * 2), "r"(MMA_IDESC), "r"(0u), "r"(acc0)
                            : "memory");
                        // lo * hi  (A lo cols at +16)
                        asm volatile(
                            "{ .reg .pred p; setp.ne.u32 p, %5, 0;"
                            "tcgen05.mma.cta_group::1.kind::f16 [%0], [%1], %2, %3, {%4, %4, %4, %4}, p; }"
                            :: "r"(acc_t), "r"(aslot + 16 + ks * 8),
                               "l"(bd + ks * 2), "r"(MMA_IDESC), "r"(0u), "r"(1u)
                            : "memory");
                        // hi * lo  (B lo half at +64B = +4 desc units)
                        asm volatile(
                            "{ .reg .pred p; setp.ne.u32 p, %5, 0;"
                            "tcgen05.mma.cta_group::1.kind::f16 [%0], [%1], %2, %3, {%4, %4, %4, %4}, p; }"
                            :: "r"(acc_t), "r"(aslot + ks * 8),
                               "l"(bd + 4 + ks * 2), "r"(MMA_IDESC), "r"(0u), "r"(1u)
                            : "memory");
                    }
                }
                if (kt == NK - 1)
                    asm volatile("tcgen05.commit.cta_group::1.mbarrier::arrive::one.shared::cluster.b64 [%0];"
                                 :: "r"(sb + OFF_MMADONE) : "memory");
                else
                    asm volatile("tcgen05.commit.cta_group::1.mbarrier::arrive::one.shared::cluster.b64 [%0];"
                                 :: "r"(sb + OFF_EMPTY(s)) : "memory");
            }
        }

        // 2. Gate on MMA(kt-1) done: frees SMEM stage (kt+2)%3 for reload AND
        //    TMEM A slot (kt+1)&1 for the next convert.
        if (kt >= 1) {
            MBAR_WAIT(sb + OFF_EMPTY((kt - 1) % STAGES), (((kt - 1) / STAGES) & 1));
        }

        // 3. Prefetch stage kt+2 (empty commit when out of range keeps the
        //    cp.async group bookkeeping uniform for the CP_WAIT below).
        if (kt + 2 < NK) load_stage((kt + 2) % STAGES, kt + 2);
        CP_COMMIT();

        // 4. Wait for stage kt+1 data, then convert its A into the free slot.
        //    Overlaps with the tensor unit executing MMA(kt).
        if (kt + 1 < NK) {
            CP_WAIT(1);
            __syncthreads();   // stage kt+1 tiles visible to all threads
            conv_A(kt + 1);
        }
    }

    // Epilogue: wait all MMAs, product of 3 degrees, scale, store.
    MBAR_WAIT(sb + OFF_MMADONE, 0);
    asm volatile("tcgen05.fence::after_thread_sync;" ::: "memory");

    float scale = g_scale;

    #define TC_LD_X32(r, tmem_addr) \
        asm volatile( \
            "tcgen05.ld.sync.aligned.32x32b.x32.b32 " \
            "{%0, %1, %2, %3, %4, %5, %6, %7, " \
            " %8, %9, %10, %11, %12, %13, %14, %15, " \
            " %16, %17, %18, %19, %20, %21, %22, %23, " \
            " %24, %25, %26, %27, %28, %29, %30, %31}, [%32];" \
            : "=r"((r)[0]),  "=r"((r)[1]),  "=r"((r)[2]),  "=r"((r)[3]), \
              "=r"((r)[4]),  "=r"((r)[5]),  "=r"((r)[6]),  "=r"((r)[7]), \
              "=r"((r)[8]),  "=r"((r)[9]),  "=r"((r)[10]), "=r"((r)[11]), \
              "=r"((r)[12]), "=r"((r)[13]), "=r"((r)[14]), "=r"((r)[15]), \
              "=r"((r)[16]), "=r"((r)[17]), "=r"((r)[18]), "=r"((r)[19]), \
              "=r"((r)[20]), "=r"((r)[21]), "=r"((r)[22]), "=r"((r)[23]), \
              "=r"((r)[24]), "=r"((r)[25]), "=r"((r)[26]), "=r"((r)[27]), \
              "=r"((r)[28]), "=r"((r)[29]), "=r"((r)[30]), "=r"((r)[31]) \
            : "r"(tmem_addr))

    float* orow = out + (size_t)(m0 + wid * 32 + lid) * DFEAT + n0;
    #pragma unroll
    for (int c = 0; c < TN / 32; c++) {
        uint32_t r0[32], r1[32], r2[32];
        TC_LD_X32(r0, tmem + TMEM_ACC(0) + c * 32);
        TC_LD_X32(r1, tmem + TMEM_ACC(1) + c * 32);
        TC_LD_X32(r2, tmem + TMEM_ACC(2) + c * 32);
        asm volatile("tcgen05.wait::ld.sync.aligned;" ::: "memory");
        float f[32];
        #pragma unroll
        for (int j = 0; j < 32; j++) {
            f[j] = __uint_as_float(r0[j]) * __uint_as_float(r1[j]) *
                   __uint_as_float(r2[j]) * scale;
        }
        #pragma unroll
        for (int q = 0; q < 8; q++) {
            float4 v = make_float4(f[q * 4], f[q * 4 + 1], f[q * 4 + 2], f[q * 4 + 3]);
            *reinterpret_cast<float4*>(orow + c * 32 + q * 4) = v;
        }
    }

    asm volatile("tcgen05.fence::before_thread_sync;" ::: "memory");
    __syncthreads();
    if (wid == 0) {
        asm volatile("tcgen05.dealloc.cta_group::1.sync.aligned.b32 %0, %1;"
                     :: "r"(tmem), "r"((uint32_t)TMEM_COLS));
    }
    #undef MBAR_WAIT
    #undef TC_ST_X16
    #undef TC_LD_X32

#else
    // ------------------------------------------------------------------
    // Fallback path (base sm_103): cp.async + ldmatrix + mma.sync, same
    // 3-term fp16 split. 4 passes over 32-col n-slices of the 128x128 tile.
    // ------------------------------------------------------------------
    extern __shared__ char smem[];
    uint32_t sb = smem_u32(smem);
    int tid  = threadIdx.x;
    int wid  = tid >> 5;
    int lane = tid & 31;
    int n0, m0;
    tile_coords((int)blockIdx.x, &n0, &m0);

    float scale = g_scale;

    auto load_stage_fb = [&](int s, int kt, int p) {
        uint32_t base = sb + SMEM_TILES + s * STAGE_BYTES;
        const __half* ah = g_xh + (size_t)m0 * DIN + kt * BK;
        const __half* al = g_xl + (size_t)m0 * DIN + kt * BK;
        #pragma unroll
        for (int c = tid; c < 1024; c += 128) {
            int row = c >> 3, ch = c & 7;
            uint32_t off = (uint32_t)(row << 7) | (uint32_t)(ch << 4);
            const __half* src = (ch < 4) ? (ah + (size_t)row * DIN + ch * 8)
                                         : (al + (size_t)row * DIN + (ch - 4) * 8);
            CP_ASYNC16(base + SWZ128(off), src);
        }
        #pragma unroll
        for (int d = 0; d < DEG; d++) {
            size_t brow = (size_t)d * DFEAT + n0 + 32 * p;
            const __half* bh = g_wh + brow * DIN + kt * BK;
            const __half* bl = g_wl + brow * DIN + kt * BK;
            uint32_t tb = base + KTILE_A + d * KTILE_B;
            #pragma unroll
            for (int j = 0; j < 2; j++) {
                int c = tid + 128 * j;          // 0..255 -> 32 rows x 8 chunks
                int row = c >> 3, ch = c & 7;
                uint32_t off = (uint32_t)(row << 7) | (uint32_t)(ch << 4);
                const __half* src = (ch < 4) ? (bh + (size_t)row * DIN + ch * 8)
                                             : (bl + (size_t)row * DIN + (ch - 4) * 8);
                CP_ASYNC16(tb + SWZ128(off), src);
            }
        }
    };

    int lr = lane & 15;
    int lc = lane >> 4;

    for (int p = 0; p < 4; p++) {
        float acc[DEG][2][4][4];
        #pragma unroll
        for (int d = 0; d < DEG; d++)
            #pragma unroll
            for (int mt = 0; mt < 2; mt++)
                #pragma unroll
                for (int nt = 0; nt < 4; nt++)
                    #pragma unroll
                    for (int r = 0; r < 4; r++) acc[d][mt][nt][r] = 0.0f;

        #pragma unroll
        for (int s = 0; s < STAGES - 1; s++) {
            load_stage_fb(s, s, p);
            CP_COMMIT();
        }

        for (int kt = 0; kt < NK; kt++) {
            CP_WAIT(STAGES - 2);
            __syncthreads();
            int s = kt % STAGES;
            uint32_t abase = sb + SMEM_TILES + s * STAGE_BYTES;

            #pragma unroll
            for (int ks = 0; ks < 2; ks++) {
                uint32_t a_hi[2][4], a_lo[2][4];
                #pragma unroll
                for (int mt = 0; mt < 2; mt++) {
                    uint32_t row = 32 * wid + 16 * mt + lr;
                    uint32_t byt = (uint32_t)(ks * 32 + lc * 16);
                    uint32_t addr_h = abase + SWZ128((row << 7) | byt);
                    uint32_t addr_l = abase + SWZ128((row << 7) | (64 + byt));
                    asm volatile(
                        "ldmatrix.sync.aligned.m8n8.x4.shared.b16 {%0,%1,%2,%3}, [%4];"
                        : "=r"(a_hi[mt][0]), "=r"(a_hi[mt][1]), "=r"(a_hi[mt][2]), "=r"(a_hi[mt][3])
                        : "r"(addr_h));
                    asm volatile(
                        "ldmatrix.sync.aligned.m8n8.x4.shared.b16 {%0,%1,%2,%3}, [%4];"
                        : "=r"(a_lo[mt][0]), "=r"(a_lo[mt][1]), "=r"(a_lo[mt][2]), "=r"(a_lo[mt][3])
                        : "r"(addr_l));
                }
                #pragma unroll
                for (int d = 0; d < DEG; d++) {
                    uint32_t bbase = abase + KTILE_A + d * KTILE_B;
                    uint32_t b_hi[2][4], b_lo[2][4];
                    #pragma unroll
                    for (int h = 0; h < 2; h++) {
                        uint32_t row = 16 * h + lr;
                        uint32_t byt = (uint32_t)(ks * 32 + lc * 16);
                        uint32_t addr_h = bbase + SWZ128((row << 7) | byt);
                        uint32_t addr_l = bbase + SWZ128((row << 7) | (64 + byt));
                        asm volatile(
                            "ldmatrix.sync.aligned.m8n8.x4.shared.b16 {%0,%1,%2,%3}, [%4];"
                            : "=r"(b_hi[h][0]), "=r"(b_hi[h][1]), "=r"(b_hi[h][2]), "=r"(b_hi[h][3])
                            : "r"(addr_h));
                        asm volatile(
                            "ldmatrix.sync.aligned.m8n8.x4.shared.b16 {%0,%1,%2,%3}, [%4];"
                            : "=r"(b_lo[h][0]), "=r"(b_lo[h][1]), "=r"(b_lo[h][2]), "=r"(b_lo[h][3])
                            : "r"(addr_l));
                    }
                    #pragma unroll
                    for (int mt = 0; mt < 2; mt++) {
                        #pragma unroll
                        for (int nt = 0; nt < 4; nt++) {
                            int h = nt >> 1, lo = nt & 1;
                            float* c = acc[d][mt][nt];
                            asm volatile(
                                "mma.sync.aligned.m16n8k16.row.col.f32.f16.f16.f32 "
                                "{%0,%1,%2,%3}, {%4,%5,%6,%7}, {%8,%9}, {%0,%1,%2,%3};"
                                : "+f"(c[0]), "+f"(c[1]), "+f"(c[2]), "+f"(c[3])
                                : "r"(a_hi[mt][0]), "r"(a_hi[mt][1]), "r"(a_hi[mt][2]), "r"(a_hi[mt][3]),
                                  "r"(b_hi[h][lo]), "r"(b_hi[h][lo + 2]));
                            asm volatile(
                                "mma.sync.aligned.m16n8k16.row.col.f32.f16.f16.f32 "
                                "{%0,%1,%2,%3}, {%4,%5,%6,%7}, {%8,%9}, {%0,%1,%2,%3};"
                                : "+f"(c[0]), "+f"(c[1]), "+f"(c[2]), "+f"(c[3])
                                : "r"(a_lo[mt][0]), "r"(a_lo[mt][1]), "r"(a_lo[mt][2]), "r"(a_lo[mt][3]),
                                  "r"(b_hi[h][lo]), "r"(b_hi[h][lo + 2]));
                            asm volatile(
                                "mma.sync.aligned.m16n8k16.row.col.f32.f16.f16.f32 "
                                "{%0,%1,%2,%3}, {%4,%5,%6,%7}, {%8,%9}, {%0,%1,%2,%3};"
                                : "+f"(c[0]), "+f"(c[1]), "+f"(c[2]), "+f"(c[3])
                                : "r"(a_hi[mt][0]), "r"(a_hi[mt][1]), "r"(a_hi[mt][2]), "r"(a_hi[mt][3]),
                                  "r"(b_lo[h][lo]), "r"(b_lo[h][lo + 2]));
                        }
                    }
                }
            }
            __syncthreads();
            int nk = kt + STAGES - 1;
            if (nk < NK) load_stage_fb(nk % STAGES, nk, p);
            CP_COMMIT();
        }
        CP_WAIT(0);
        __syncthreads();

        int g = lane >> 2, t = lane & 3;
        #pragma unroll
        for (int mt = 0; mt < 2; mt++) {
            #pragma unroll
            for (int nt = 0; nt < 4; nt++) {
                int row = m0 + 32 * wid + 16 * mt + g;
                int col = n0 + 32 * p + 8 * nt + 2 * t;
                float p0 = acc[0][mt][nt][0] * acc[1][mt][nt][0] * acc[2][mt][nt][0] * scale;
                float p1 = acc[0][mt][nt][1] * acc[1][mt][nt][1] * acc[2][mt][nt][1] * scale;
                float p2 = acc[0][mt][nt][2] * acc[1][mt][nt][2] * acc[2][mt][nt][2] * scale;
                float p3 = acc[0][mt][nt][3] * acc[1][mt][nt][3] * acc[2][mt][nt][3] * scale;
                *reinterpret_cast<float2*>(out + (size_t)row * DFEAT + col) =
                    make_float2(p0, p1);
                *reinterpret_cast<float2*>(out + (size_t)(row + 8) * DFEAT + col) =
                    make_float2(p2, p3);
            }
        }
    }
#endif
}

// ============================================================================
// Launch
// ============================================================================
extern "C" void kernel_launch(void* const* d_in, const int* in_sizes, int n_in,
                              void* d_out, int out_size) {
    const float* x   = (const float*)d_in[0];
    const float* W   = (const float*)d_in[1];
    const float* lls = (const float*)d_in[2];
    const float* lv  = (const float*)d_in[3];
    float* out = (float*)d_out;

    convert_x_kernel<<<(BATCH * (size_t)DIN) / (4 * 256), 256>>>(x, lls);
    convert_w_kernel<<<dim3(DFEAT / 32, DIN / 32, DEG), dim3(32, 32)>>>(W);
    scale_kernel<<<1, 1>>>(lv);

    cudaFuncSetAttribute(sketch_kernel,
                         cudaFuncAttributeMaxDynamicSharedMemorySize, SMEM_TOTAL);
    // 1-D grid with band rasterization (see tile_coords)
    sketch_kernel<<<NTILES_N * NTILES_M, 128, SMEM_TOTAL>>>(out);
}

// round 12
// speedup vs baseline: 1.2368x; 1.1634x over previous
#include <cuda_runtime.h>
#include <cuda.h>
#include <cuda_fp16.h>
#include <cstdint>
#include <cmath>

// ============================================================================
// Problem constants
// ============================================================================
#define BATCH  16384
#define DIN    1024
#define DFEAT  4096
#define DEG    3

// Tiling: 128(m) x 128(n) per CTA, TS-mode (A in TMEM), TMA-fed stages.
#define TM 128
#define TN 128
#define BK 32          // 32 halves; combined row = [hi 64B | lo 64B] = 128B
#define NK (DIN / BK)  // 32 K-chunks
#define STAGES 3

#define NTILES_N (DFEAT / TN)    // 32
#define NTILES_M (BATCH / TM)    // 128
#define NBAND    8

#define KTILE_A  16384                      // 128 rows x 128B
#define KTILE_B  16384
#define STAGE_BYTES (KTILE_A + DEG * KTILE_B)   // 65536
#define SMEM_TILES  1024
#define SMEM_TOTAL  (SMEM_TILES + STAGES * STAGE_BYTES)   // 197632

// SMEM control offsets
#define OFF_TMEM     0
#define OFF_EMPTY(s) (16 + 8 * (s))
#define OFF_MMADONE  48
#define OFF_FULL(s)  (56 + 8 * (s))

// TMEM: 3 fp32 accumulators x 128 cols; 2 A slots x 32 cols at 384/416
#define TMEM_ACC(d)   ((d) * 128)
#define TMEM_ASLOT(i) (384 + (i) * 32)
#define TMEM_COLS 512

// idesc kind::f16: dtype=F32 (bit4), N>>3 @[17:22], M>>4 @[24:28]
static constexpr uint32_t MMA_IDESC =
    (1u << 4) | ((TN / 8) << 17) | ((TM / 16) << 24);

// ============================================================================
// Scratch: combined interleaved fp16 pairs.
// g_xc[(m*NK + c)*64 + p]      = hi of x[m][c*32+p],  +32 -> lo
// g_wc[((d*DFEAT+o)*NK+c)*64+p] = hi of W[d][c*32+p][o], +32 -> lo
// ============================================================================
__device__ __half g_xc[(size_t)BATCH * NK * 64];
__device__ __half g_wc[(size_t)DEG * DFEAT * NK * 64];
__device__ float  g_scale;

// ============================================================================
// Helpers
// ============================================================================
__device__ __forceinline__ uint32_t smem_u32(const void* p) {
    uint32_t a;
    asm("{ .reg .u64 t; cvta.to.shared.u64 t, %1; cvt.u32.u64 %0, t; }"
        : "=r"(a) : "l"(p));
    return a;
}

#define CP_ASYNC16(dst, src) \
    asm volatile("cp.async.cg.shared.global [%0], [%1], 16;" \
                 :: "r"(dst), "l"(src) : "memory")
#define CP_COMMIT() asm volatile("cp.async.commit_group;" ::: "memory")
#define CP_WAIT(n)  asm volatile("cp.async.wait_group %0;" :: "n"(n) : "memory")

#define SWZ128(off) ((off) ^ (((off) >> 3) & 0x70))

__device__ __forceinline__ void tile_coords(int bid, int* n0, int* m0) {
    int band = bid / (NBAND * NTILES_M);
    int r    = bid % (NBAND * NTILES_M);
    int nb   = band * NBAND + (r % NBAND);
    int mb   = r / NBAND;
    *n0 = nb * TN;
    *m0 = mb * TM;
}

// ============================================================================
// Pre-pass 1: x -> combined (hi|lo) layout, scaled by exp(-ll)
// ============================================================================
__global__ void convert_x_kernel(const float* __restrict__ x,
                                 const float* __restrict__ lls) {
    float s = expf(-lls[0]);
    size_t e = ((size_t)blockIdx.x * blockDim.x + threadIdx.x) * 4;
    float4 v = *reinterpret_cast<const float4*>(x + e);
    float f[4] = {v.x * s, v.y * s, v.z * s, v.w * s};
    __half hi[4], lo[4];
    #pragma unroll
    for (int j = 0; j < 4; j++) {
        hi[j] = __float2half_rn(f[j]);
        lo[j] = __float2half_rn(f[j] - __half2float(hi[j]));
    }
    size_t m = e >> 10;           // / DIN
    int    k = (int)(e & 1023);
    int    c = k >> 5, pos = k & 31;
    size_t base = ((size_t)m * NK + c) * 64;
    *reinterpret_cast<uint2*>(g_xc + base + pos)      = *reinterpret_cast<uint2*>(hi);
    *reinterpret_cast<uint2*>(g_xc + base + 32 + pos) = *reinterpret_cast<uint2*>(lo);
}

// ============================================================================
// Pre-pass 2: W [d][i][o] -> combined transposed (hi|lo) layout
// ============================================================================
__global__ void convert_w_kernel(const float* __restrict__ W) {
    __shared__ float tile[32][33];
    int d  = blockIdx.z;
    int o0 = blockIdx.x * 32;
    int i0 = blockIdx.y * 32;
    int tx = threadIdx.x, ty = threadIdx.y;
    tile[ty][tx] = W[((size_t)d * DIN + (i0 + ty)) * DFEAT + (o0 + tx)];
    __syncthreads();
    float f = tile[tx][ty];               // = W[d][i0+tx][o0+ty]
    __half hi = __float2half_rn(f);
    __half lo = __float2half_rn(f - __half2float(hi));
    size_t base = (((size_t)d * DFEAT + (o0 + ty)) * NK + (i0 >> 5)) * 64;
    g_wc[base + tx]      = hi;
    g_wc[base + 32 + tx] = lo;
}

// ============================================================================
// Pre-pass 3: output scale
// ============================================================================
__global__ void scale_kernel(const float* __restrict__ lv) {
    g_scale = 0.015625f * expf(0.5f * lv[0]);
}

// ============================================================================
// Main fused kernel: TMA-fed, TS-mode, 3-term fp16-split, fused epilogue.
// ============================================================================
__global__ void __launch_bounds__(128, 1)
sketch_kernel(float* __restrict__ out,
              const __grid_constant__ CUtensorMap map_x,
              const __grid_constant__ CUtensorMap map_w) {
#if defined(__CUDA_ARCH_FEAT_SM103_ALL) || defined(__CUDA_ARCH_FEAT_SM100_ALL)
    extern __shared__ char smem[];
    uint32_t sb = smem_u32(smem);
    int tid = threadIdx.x;
    int wid = tid >> 5, lid = tid & 31;
    int n0, m0;
    tile_coords((int)blockIdx.x, &n0, &m0);
    uint32_t warp_off = ((uint32_t)wid) << 21;

    if (wid == 0) {
        asm volatile("tcgen05.alloc.cta_group::1.sync.aligned.shared::cta.b32 [%0], %1;"
                     :: "r"(sb + OFF_TMEM), "r"((uint32_t)TMEM_COLS) : "memory");
        asm volatile("tcgen05.relinquish_alloc_permit.cta_group::1.sync.aligned;");
    }
    if (tid == 0) {
        #pragma unroll
        for (int s = 0; s < STAGES; s++) {
            asm volatile("mbarrier.init.shared.b64 [%0], %1;"
                         :: "r"(sb + OFF_EMPTY(s)), "r"(1) : "memory");
            asm volatile("mbarrier.init.shared.b64 [%0], %1;"
                         :: "r"(sb + OFF_FULL(s)), "r"(1) : "memory");
        }
        asm volatile("mbarrier.init.shared.b64 [%0], %1;"
                     :: "r"(sb + OFF_MMADONE), "r"(1) : "memory");
    }
    __syncthreads();
    uint32_t tmem;
    asm volatile("ld.shared.b32 %0, [%1];" : "=r"(tmem) : "r"(sb + OFF_TMEM));

    #define MBAR_WAIT(addr, parity) do {                                           \
        uint32_t _m = (addr), _p = (parity), _d;                                   \
        asm volatile("{ .reg .pred p; "                                            \
            "mbarrier.try_wait.parity.acquire.cta.shared::cta.b64 p, [%1], %2; "   \
            "selp.b32 %0, 1, 0, p; }" : "=r"(_d) : "r"(_m), "r"(_p) : "memory");   \
        if (!_d) {                                                                 \
            asm volatile("{ .reg .pred P; L_%=: "                                  \
                "mbarrier.try_wait.parity.acquire.cta.shared::cta.b64 P, [%0], %1, 0x989680; " \
                "@P bra.uni D_%=; bra.uni L_%=; D_%=: }"                           \
                :: "r"(_m), "r"(_p) : "memory");                                   \
        }                                                                          \
    } while (0)

    #define TC_ST_X16(taddr, r)                                                    \
        asm volatile("tcgen05.st.sync.aligned.32x32b.x16.b32 [%0], "               \
            "{%1,%2,%3,%4,%5,%6,%7,%8,%9,%10,%11,%12,%13,%14,%15,%16};"            \
            :: "r"(taddr),                                                         \
               "r"((r)[0]),  "r"((r)[1]),  "r"((r)[2]),  "r"((r)[3]),              \
               "r"((r)[4]),  "r"((r)[5]),  "r"((r)[6]),  "r"((r)[7]),              \
               "r"((r)[8]),  "r"((r)[9]),  "r"((r)[10]), "r"((r)[11]),             \
               "r"((r)[12]), "r"((r)[13]), "r"((r)[14]), "r"((r)[15]) : "memory")

    #define TMA_LD(smemaddr, map, c1, c2, mbar)                                    \
        asm volatile("cp.async.bulk.tensor.3d.shared::cta.global.tile"             \
            ".mbarrier::complete_tx::bytes [%0], [%1, {%2, %3, %4}], [%5];"        \
            :: "r"(smemaddr), "l"(map), "r"(0), "r"(c1), "r"(c2),                  \
               "r"(mbar) : "memory")

    // Issue all 4 TMA loads for chunk kt into stage slot kt%3 (thread 0 only).
    auto tma_stage = [&](int kt) {
        int s = kt % STAGES;
        uint32_t base = sb + SMEM_TILES + s * STAGE_BYTES;
        uint32_t mbar = sb + OFF_FULL(s);
        asm volatile("mbarrier.arrive.expect_tx.shared.b64 _, [%0], %1;"
                     :: "r"(mbar), "r"((uint32_t)STAGE_BYTES) : "memory");
        TMA_LD(base, &map_x, kt, m0, mbar);
        #pragma unroll
        for (int d = 0; d < DEG; d++) {
            TMA_LD(base + KTILE_A + d * KTILE_B, &map_w, kt,
                   d * DFEAT + n0, mbar);
        }
    };

    // A convert: stage (kt%STAGES) SMEM -> regs -> TMEM slot (kt&1).
    auto conv_A = [&](int kt) {
        uint32_t abase = sb + SMEM_TILES + (kt % STAGES) * STAGE_BYTES;
        uint32_t slot = tmem + TMEM_ASLOT(kt & 1);
        uint32_t row = (uint32_t)tid;
        uint32_t rh[16], rl[16];
        #pragma unroll
        for (int c2 = 0; c2 < 4; c2++) {     // hi: bytes 0..63
            uint32_t addr = abase + SWZ128((row << 7) | (uint32_t)(c2 << 4));
            asm volatile("ld.shared.v4.b32 {%0,%1,%2,%3}, [%4];"
                : "=r"(rh[c2*4]), "=r"(rh[c2*4+1]), "=r"(rh[c2*4+2]), "=r"(rh[c2*4+3])
                : "r"(addr));
        }
        #pragma unroll
        for (int c2 = 0; c2 < 4; c2++) {     // lo: bytes 64..127
            uint32_t addr = abase + SWZ128((row << 7) | (uint32_t)((c2 + 4) << 4));
            asm volatile("ld.shared.v4.b32 {%0,%1,%2,%3}, [%4];"
                : "=r"(rl[c2*4]), "=r"(rl[c2*4+1]), "=r"(rl[c2*4+2]), "=r"(rl[c2*4+3])
                : "r"(addr));
        }
        TC_ST_X16(slot + warp_off, rh);
        TC_ST_X16(slot + 16 + warp_off, rl);
        asm volatile("tcgen05.wait::st.sync.aligned;" ::: "memory");
        asm volatile("tcgen05.fence::before_thread_sync;" ::: "memory");
        __syncthreads();
    };

    constexpr uint64_t DESC_BASE =
        (uint64_t(2) << 61) | (uint64_t(1) << 46) | (uint64_t(64) << 32) | (uint64_t(1) << 16);

    // Prologue: issue stages 0..2, convert A chunk 0
    if (tid == 0) {
        tma_stage(0);
        tma_stage(1);
        tma_stage(2);
    }
    MBAR_WAIT(sb + OFF_FULL(0), 0);
    conv_A(0);

    for (int kt = 0; kt < NK; kt++) {
        int s = kt % STAGES;

        // 1. Issue MMA(kt): A slot (kt&1) converted, stage s B resident
        //    (FULL(s) was acquired by all threads last iteration / prologue).
        if (wid == 0) {
            uint32_t is_elect;
            asm volatile("{ .reg .pred p; elect.sync _|p, 0xFFFFFFFF; selp.b32 %0, 1, 0, p; }"
                         : "=r"(is_elect));
            if (is_elect) {
                asm volatile("tcgen05.fence::after_thread_sync;" ::: "memory");
                uint32_t stage_base = sb + SMEM_TILES + s * STAGE_BYTES;
                uint32_t aslot = tmem + TMEM_ASLOT(kt & 1);
                #pragma unroll
                for (int d = 0; d < DEG; d++) {
                    uint32_t bb = stage_base + KTILE_A + d * KTILE_B;
                    uint64_t bd = DESC_BASE | ((uint64_t)(bb >> 4) & 0x3FFF);
                    uint32_t acc_t = tmem + TMEM_ACC(d);
                    #pragma unroll
                    for (int ks = 0; ks < 2; ks++) {
                        uint32_t acc0 = (kt > 0 || ks > 0) ? 1u : 0u;
                        asm volatile(   // hi * hi
                            "{ .reg .pred p; setp.ne.u32 p, %5, 0;"
                            "tcgen05.mma.cta_group::1.kind::f16 [%0], [%1], %2, %3, {%4, %4, %4, %4}, p; }"
                            :: "r"(acc_t), "r"(aslot + ks * 8),
                               "l"(bd + ks * 2), "r"(MMA_IDESC), "r"(0u), "r"(acc0)
                            : "memory");
                        asm volatile(   // lo * hi
                            "{ .reg .pred p; setp.ne.u32 p, %5, 0;"
                            "tcgen05.mma.cta_group::1.kind::f16 [%0], [%1], %2, %3, {%4, %4, %4, %4}, p; }"
                            :: "r"(acc_t), "r"(aslot + 16 + ks * 8),
                               "l"(bd + ks * 2), "r"(MMA_IDESC), "r"(0u), "r"(1u)
                            : "memory");
                        asm volatile(   // hi * lo (B lo half at +64B)
                            "{ .reg .pred p; setp.ne.u32 p, %5, 0;"
                            "tcgen05.mma.cta_group::1.kind::f16 [%0], [%1], %2, %3, {%4, %4, %4, %4}, p; }"
                            :: "r"(acc_t), "r"(aslot + ks * 8),
                               "l"(bd + 4 + ks * 2), "r"(MMA_IDESC), "r"(0u), "r"(1u)
                            : "memory");
                    }
                }
                if (kt == NK - 1)
                    asm volatile("tcgen05.commit.cta_group::1.mbarrier::arrive::one.shared::cluster.b64 [%0];"
                                 :: "r"(sb + OFF_MMADONE) : "memory");
                else
                    asm volatile("tcgen05.commit.cta_group::1.mbarrier::arrive::one.shared::cluster.b64 [%0];"
                                 :: "r"(sb + OFF_EMPTY(s)) : "memory");
            }
        }

        // 2. All threads: wait MMA(kt-1) drained -> frees SMEM slot (kt+2)%3
        //    for TMA reuse and TMEM A slot (kt+1)&1 for the next convert.
        if (kt >= 1) {
            MBAR_WAIT(sb + OFF_EMPTY((kt - 1) % STAGES), (((kt - 1) / STAGES) & 1));
        }

        // 3. Thread 0: prefetch chunk kt+2 (stages 0..2 covered by prologue).
        if (tid == 0 && kt + 2 >= STAGES && kt + 2 < NK) {
            tma_stage(kt + 2);
        }

        // 4. Wait stage kt+1 data; convert its A (overlaps tensor on MMA(kt)).
        if (kt + 1 < NK) {
            MBAR_WAIT(sb + OFF_FULL((kt + 1) % STAGES), (((kt + 1) / STAGES) & 1));
            conv_A(kt + 1);
        }
    }

    // Epilogue
    MBAR_WAIT(sb + OFF_MMADONE, 0);
    asm volatile("tcgen05.fence::after_thread_sync;" ::: "memory");

    float scale = g_scale;

    #define TC_LD_X32(r, tmem_addr) \
        asm volatile( \
            "tcgen05.ld.sync.aligned.32x32b.x32.b32 " \
            "{%0, %1, %2, %3, %4, %5, %6, %7, " \
            " %8, %9, %10, %11, %12, %13, %14, %15, " \
            " %16, %17, %18, %19, %20, %21, %22, %23, " \
            " %24, %25, %26, %27, %28, %29, %30, %31}, [%32];" \
            : "=r"((r)[0]),  "=r"((r)[1]),  "=r"((r)[2]),  "=r"((r)[3]), \
              "=r"((r)[4]),  "=r"((r)[5]),  "=r"((r)[6]),  "=r"((r)[7]), \
              "=r"((r)[8]),  "=r"((r)[9]),  "=r"((r)[10]), "=r"((r)[11]), \
              "=r"((r)[12]), "=r"((r)[13]), "=r"((r)[14]), "=r"((r)[15]), \
              "=r"((r)[16]), "=r"((r)[17]), "=r"((r)[18]), "=r"((r)[19]), \
              "=r"((r)[20]), "=r"((r)[21]), "=r"((r)[22]), "=r"((r)[23]), \
              "=r"((r)[24]), "=r"((r)[25]), "=r"((r)[26]), "=r"((r)[27]), \
              "=r"((r)[28]), "=r"((r)[29]), "=r"((r)[30]), "=r"((r)[31]) \
            : "r"(tmem_addr))

    float* orow = out + (size_t)(m0 + wid * 32 + lid) * DFEAT + n0;
    #pragma unroll
    for (int c = 0; c < TN / 32; c++) {
        uint32_t r0[32], r1[32], r2[32];
        TC_LD_X32(r0, tmem + TMEM_ACC(0) + c * 32);
        TC_LD_X32(r1, tmem + TMEM_ACC(1) + c * 32);
        TC_LD_X32(r2, tmem + TMEM_ACC(2) + c * 32);
        asm volatile("tcgen05.wait::ld.sync.aligned;" ::: "memory");
        float f[32];
        #pragma unroll
        for (int j = 0; j < 32; j++) {
            f[j] = __uint_as_float(r0[j]) * __uint_as_float(r1[j]) *
                   __uint_as_float(r2[j]) * scale;
        }
        #pragma unroll
        for (int q = 0; q < 8; q++) {
            float4 v = make_float4(f[q * 4], f[q * 4 + 1], f[q * 4 + 2], f[q * 4 + 3]);
            *reinterpret_cast<float4*>(orow + c * 32 + q * 4) = v;
        }
    }

    asm volatile("tcgen05.fence::before_thread_sync;" ::: "memory");
    __syncthreads();
    if (wid == 0) {
        asm volatile("tcgen05.dealloc.cta_group::1.sync.aligned.b32 %0, %1;"
                     :: "r"(tmem), "r"((uint32_t)TMEM_COLS));
    }
    #undef MBAR_WAIT
    #undef TC_ST_X16
    #undef TMA_LD
    #undef TC_LD_X32

#else
    // ------------------------------------------------------------------
    // Fallback path (base sm_103): cp.async + ldmatrix + mma.sync on the
    // combined gmem layout. 4 passes over 32-col n-slices.
    // ------------------------------------------------------------------
    extern __shared__ char smem[];
    uint32_t sb = smem_u32(smem);
    int tid  = threadIdx.x;
    int wid  = tid >> 5;
    int lane = tid & 31;
    int n0, m0;
    tile_coords((int)blockIdx.x, &n0, &m0);

    float scale = g_scale;

    auto load_stage_fb = [&](int s, int kt, int p) {
        uint32_t base = sb + SMEM_TILES + s * STAGE_BYTES;
        #pragma unroll
        for (int c = tid; c < 1024; c += 128) {
            int row = c >> 3, ch = c & 7;
            uint32_t off = (uint32_t)(row << 7) | (uint32_t)(ch << 4);
            const __half* src = g_xc + ((size_t)(m0 + row) * NK + kt) * 64 + ch * 8;
            CP_ASYNC16(base + SWZ128(off), src);
        }
        #pragma unroll
        for (int d = 0; d < DEG; d++) {
            uint32_t tb = base + KTILE_A + d * KTILE_B;
            #pragma unroll
            for (int j = 0; j < 2; j++) {
                int c = tid + 128 * j;
                int row = c >> 3, ch = c & 7;
                uint32_t off = (uint32_t)(row << 7) | (uint32_t)(ch << 4);
                const __half* src = g_wc +
                    (((size_t)d * DFEAT + n0 + 32 * p + row) * NK + kt) * 64 + ch * 8;
                CP_ASYNC16(tb + SWZ128(off), src);
            }
        }
    };

    int lr = lane & 15;
    int lc = lane >> 4;

    for (int p = 0; p < 4; p++) {
        float acc[DEG][2][4][4];
        #pragma unroll
        for (int d = 0; d < DEG; d++)
            #pragma unroll
            for (int mt = 0; mt < 2; mt++)
                #pragma unroll
                for (int nt = 0; nt < 4; nt++)
                    #pragma unroll
                    for (int r = 0; r < 4; r++) acc[d][mt][nt][r] = 0.0f;

        #pragma unroll
        for (int s = 0; s < STAGES - 1; s++) {
            load_stage_fb(s, s, p);
            CP_COMMIT();
        }

        for (int kt = 0; kt < NK; kt++) {
            CP_WAIT(STAGES - 2);
            __syncthreads();
            int s = kt % STAGES;
            uint32_t abase = sb + SMEM_TILES + s * STAGE_BYTES;

            #pragma unroll
            for (int ks = 0; ks < 2; ks++) {
                uint32_t a_hi[2][4], a_lo[2][4];
                #pragma unroll
                for (int mt = 0; mt < 2; mt++) {
                    uint32_t row = 32 * wid + 16 * mt + lr;
                    uint32_t byt = (uint32_t)(ks * 32 + lc * 16);
                    uint32_t addr_h = abase + SWZ128((row << 7) | byt);
                    uint32_t addr_l = abase + SWZ128((row << 7) | (64 + byt));
                    asm volatile(
                        "ldmatrix.sync.aligned.m8n8.x4.shared.b16 {%0,%1,%2,%3}, [%4];"
                        : "=r"(a_hi[mt][0]), "=r"(a_hi[mt][1]), "=r"(a_hi[mt][2]), "=r"(a_hi[mt][3])
                        : "r"(addr_h));
                    asm volatile(
                        "ldmatrix.sync.aligned.m8n8.x4.shared.b16 {%0,%1,%2,%3}, [%4];"
                        : "=r"(a_lo[mt][0]), "=r"(a_lo[mt][1]), "=r"(a_lo[mt][2]), "=r"(a_lo[mt][3])
                        : "r"(addr_l));
                }
                #pragma unroll
                for (int d = 0; d < DEG; d++) {
                    uint32_t bbase = abase + KTILE_A + d * KTILE_B;
                    uint32_t b_hi[2][4], b_lo[2][4];
                    #pragma unroll
                    for (int h = 0; h < 2; h++) {
                        uint32_t row = 16 * h + lr;
                        uint32_t byt = (uint32_t)(ks * 32 + lc * 16);
                        uint32_t addr_h = bbase + SWZ128((row << 7) | byt);
                        uint32_t addr_l = bbase + SWZ128((row << 7) | (64 + byt));
                        asm volatile(
                            "ldmatrix.sync.aligned.m8n8.x4.shared.b16 {%0,%1,%2,%3}, [%4];"
                            : "=r"(b_hi[h][0]), "=r"(b_hi[h][1]), "=r"(b_hi[h][2]), "=r"(b_hi[h][3])
                            : "r"(addr_h));
                        asm volatile(
                            "ldmatrix.sync.aligned.m8n8.x4.shared.b16 {%0,%1,%2,%3}, [%4];"
                            : "=r"(b_lo[h][0]), "=r"(b_lo[h][1]), "=r"(b_lo[h][2]), "=r"(b_lo[h][3])
                            : "r"(addr_l));
                    }
                    #pragma unroll
                    for (int mt = 0; mt < 2; mt++) {
                        #pragma unroll
                        for (int nt = 0; nt < 4; nt++) {
                            int h = nt >> 1, lo = nt & 1;
                            float* c = acc[d][mt][nt];
                            asm volatile(
                                "mma.sync.aligned.m16n8k16.row.col.f32.f16.f16.f32 "
                                "{%0,%1,%2,%3}, {%4,%5,%6,%7}, {%8,%9}, {%0,%1,%2,%3};"
                                : "+f"(c[0]), "+f"(c[1]), "+f"(c[2]), "+f"(c[3])
                                : "r"(a_hi[mt][0]), "r"(a_hi[mt][1]), "r"(a_hi[mt][2]), "r"(a_hi[mt][3]),
                                  "r"(b_hi[h][lo]), "r"(b_hi[h][lo + 2]));
                            asm volatile(
                                "mma.sync.aligned.m16n8k16.row.col.f32.f16.f16.f32 "
                                "{%0,%1,%2,%3}, {%4,%5,%6,%7}, {%8,%9}, {%0,%1,%2,%3};"
                                : "+f"(c[0]), "+f"(c[1]), "+f"(c[2]), "+f"(c[3])
                                : "r"(a_lo[mt][0]), "r"(a_lo[mt][1]), "r"(a_lo[mt][2]), "r"(a_lo[mt][3]),
                                  "r"(b_hi[h][lo]), "r"(b_hi[h][lo + 2]));
                            asm volatile(
                                "mma.sync.aligned.m16n8k16.row.col.f32.f16.f16.f32 "
                                "{%0,%1,%2,%3}, {%4,%5,%6,%7}, {%8,%9}, {%0,%1,%2,%3};"
                                : "+f"(c[0]), "+f"(c[1]), "+f"(c[2]), "+f"(c[3])
                                : "r"(a_hi[mt][0]), "r"(a_hi[mt][1]), "r"(a_hi[mt][2]), "r"(a_hi[mt][3]),
                                  "r"(b_lo[h][lo]), "r"(b_lo[h][lo + 2]));
                        }
                    }
                }
            }
            __syncthreads();
            int nk = kt + STAGES - 1;
            if (nk < NK) load_stage_fb(nk % STAGES, nk, p);
            CP_COMMIT();
        }
        CP_WAIT(0);
        __syncthreads();

        int g = lane >> 2, t = lane & 3;
        #pragma unroll
        for (int mt = 0; mt < 2; mt++) {
            #pragma unroll
            for (int nt = 0; nt < 4; nt++) {
                int row = m0 + 32 * wid + 16 * mt + g;
                int col = n0 + 32 * p + 8 * nt + 2 * t;
                float p0 = acc[0][mt][nt][0] * acc[1][mt][nt][0] * acc[2][mt][nt][0] * scale;
                float p1 = acc[0][mt][nt][1] * acc[1][mt][nt][1] * acc[2][mt][nt][1] * scale;
                float p2 = acc[0][mt][nt][2] * acc[1][mt][nt][2] * acc[2][mt][nt][2] * scale;
                float p3 = acc[0][mt][nt][3] * acc[1][mt][nt][3] * acc[2][mt][nt][3] * scale;
                *reinterpret_cast<float2*>(out + (size_t)row * DFEAT + col) =
                    make_float2(p0, p1);
                *reinterpret_cast<float2*>(out + (size_t)(row + 8) * DFEAT + col) =
                    make_float2(p2, p3);
            }
        }
    }
#endif
}

// ============================================================================
// Launch: encode tensormaps via driver entry point (no -lcuda link needed)
// ============================================================================
typedef CUresult (*PFN_EncodeTiled)(
    CUtensorMap*, CUtensorMapDataType, cuuint32_t, void*,
    const cuuint64_t*, const cuuint64_t*, const cuuint32_t*, const cuuint32_t*,
    CUtensorMapInterleave, CUtensorMapSwizzle, CUtensorMapL2promotion,
    CUtensorMapFloatOOBfill);

extern "C" void kernel_launch(void* const* d_in, const int* in_sizes, int n_in,
                              void* d_out, int out_size) {
    const float* x   = (const float*)d_in[0];
    const float* W   = (const float*)d_in[1];
    const float* lls = (const float*)d_in[2];
    const float* lv  = (const float*)d_in[3];
    float* out = (float*)d_out;

    convert_x_kernel<<<(BATCH * (size_t)DIN) / (4 * 256), 256>>>(x, lls);
    convert_w_kernel<<<dim3(DFEAT / 32, DIN / 32, DEG), dim3(32, 32)>>>(W);
    scale_kernel<<<1, 1>>>(lv);

    // Tensormaps over the combined scratch arrays
    PFN_EncodeTiled encode = nullptr;
    cudaDriverEntryPointQueryResult qr;
    cudaGetDriverEntryPoint("cuTensorMapEncodeTiled", (void**)&encode,
                            cudaEnableDefault, &qr);

    void *p_xc = nullptr, *p_wc = nullptr;
    cudaGetSymbolAddress(&p_xc, g_xc);
    cudaGetSymbolAddress(&p_wc, g_wc);

    CUtensorMap map_x{}, map_w{};
    {
        cuuint64_t dims[3]    = {64, NK, BATCH};
        cuuint64_t strides[2] = {128, 128ull * NK};
        cuuint32_t box[3]     = {64, 1, 128};
        cuuint32_t es[3]      = {1, 1, 1};
        encode(&map_x, CU_TENSOR_MAP_DATA_TYPE_FLOAT16, 3, p_xc,
               dims, strides, box, es,
               CU_TENSOR_MAP_INTERLEAVE_NONE, CU_TENSOR_MAP_SWIZZLE_128B,
               CU_TENSOR_MAP_L2_PROMOTION_L2_128B,
               CU_TENSOR_MAP_FLOAT_OOB_FILL_NONE);
    }
    {
        cuuint64_t dims[3]    = {64, NK, (cuuint64_t)DEG * DFEAT};
        cuuint64_t strides[2] = {128, 128ull * NK};
        cuuint32_t box[3]     = {64, 1, 128};
        cuuint32_t es[3]      = {1, 1, 1};
        encode(&map_w, CU_TENSOR_MAP_DATA_TYPE_FLOAT16, 3, p_wc,
               dims, strides, box, es,
               CU_TENSOR_MAP_INTERLEAVE_NONE, CU_TENSOR_MAP_SWIZZLE_128B,
               CU_TENSOR_MAP_L2_PROMOTION_L2_128B,
               CU_TENSOR_MAP_FLOAT_OOB_FILL_NONE);
    }

    cudaFuncSetAttribute(sketch_kernel,
                         cudaFuncAttributeMaxDynamicSharedMemorySize, SMEM_TOTAL);
    sketch_kernel<<<NTILES_N * NTILES_M, 128, SMEM_TOTAL>>>(out, map_x, map_w);
}

// round 13
// speedup vs baseline: 1.5921x; 1.2872x over previous
#include <cuda_runtime.h>
#include <cuda.h>
#include <cuda_fp16.h>
#include <cstdint>
#include <cmath>

// ============================================================================
// Problem constants
// ============================================================================
#define BATCH  16384
#define DIN    1024
#define DFEAT  4096
#define DEG    3

// cg2 tiling: a 2-CTA cluster computes 256(m) x 128(n). Each CTA holds its
// 128-row A half and its 64-row B half (N-split per test_2cta finding).
// SS-mode MMA (A and B both SMEM descriptors) -> no A convert in the loop.
#define TMC 256        // cluster m tile
#define TN  128        // n tile
#define BK  32         // 32 halves; combined row = [hi 64B | lo 64B] = 128B
#define NK  (DIN / BK) // 32 K-chunks
#define STAGES 4

#define NTILES_N (DFEAT / TN)     // 32
#define NTILES_M (BATCH / TMC)    // 64
#define NBAND    8

#define KTILE_A  16384                      // 128 rows x 128B (A half)
#define KTILE_B  8192                       // 64 rows x 128B (B half)
#define STAGE_BYTES (KTILE_A + DEG * KTILE_B)   // 40960
#define SMEM_TILES  1024
#define SMEM_TOTAL  (SMEM_TILES + STAGES * STAGE_BYTES)   // 164864

// SMEM control offsets
#define OFF_TMEM     0
#define OFF_EMPTY(s) (16 + 8 * (s))
#define OFF_MMADONE  56
#define OFF_FULL(s)  (64 + 8 * (s))

// TMEM: 3 fp32 accumulators x 128 cols per CTA (its 128-row half of D)
#define TMEM_ACC(d) ((d) * 128)
#define TMEM_COLS 512

// idesc kind::f16 cg2: dtype=F32 (bit4), N>>3 @[17:22], M_total>>4 @[24:28]
static constexpr uint32_t MMA_IDESC =
    (1u << 4) | ((TN / 8) << 17) | ((TMC / 16) << 24);

// ============================================================================
// Scratch: combined interleaved fp16 pairs (row = [hi 32 | lo 32] halves).
// ============================================================================
__device__ __half g_xc[(size_t)BATCH * NK * 64];
__device__ __half g_wc[(size_t)DEG * DFEAT * NK * 64];
__device__ float  g_scale;

// ============================================================================
// Helpers
// ============================================================================
__device__ __forceinline__ uint32_t smem_u32(const void* p) {
    uint32_t a;
    asm("{ .reg .u64 t; cvta.to.shared.u64 t, %1; cvt.u32.u64 %0, t; }"
        : "=r"(a) : "l"(p));
    return a;
}

#define CP_ASYNC16(dst, src) \
    asm volatile("cp.async.cg.shared.global [%0], [%1], 16;" \
                 :: "r"(dst), "l"(src) : "memory")
#define CP_COMMIT() asm volatile("cp.async.commit_group;" ::: "memory")
#define CP_WAIT(n)  asm volatile("cp.async.wait_group %0;" :: "n"(n) : "memory")

#define SWZ128(off) ((off) ^ (((off) >> 3) & 0x70))

// Cluster (pair) raster: band of NBAND n-tiles, m-major inside the band.
__device__ __forceinline__ void cl_coords(int cl, int* nt, int* mt) {
    int band = cl / (NBAND * NTILES_M);
    int r    = cl % (NBAND * NTILES_M);
    *nt = band * NBAND + (r % NBAND);
    *mt = r / NBAND;
}

// ============================================================================
// Pre-pass 1: x -> combined (hi|lo) layout, scaled by exp(-ll)
// ============================================================================
__global__ void convert_x_kernel(const float* __restrict__ x,
                                 const float* __restrict__ lls) {
    float s = expf(-lls[0]);
    size_t e = ((size_t)blockIdx.x * blockDim.x + threadIdx.x) * 4;
    float4 v = *reinterpret_cast<const float4*>(x + e);
    float f[4] = {v.x * s, v.y * s, v.z * s, v.w * s};
    __half hi[4], lo[4];
    #pragma unroll
    for (int j = 0; j < 4; j++) {
        hi[j] = __float2half_rn(f[j]);
        lo[j] = __float2half_rn(f[j] - __half2float(hi[j]));
    }
    size_t m = e >> 10;
    int    k = (int)(e & 1023);
    int    c = k >> 5, pos = k & 31;
    size_t base = ((size_t)m * NK + c) * 64;
    *reinterpret_cast<uint2*>(g_xc + base + pos)      = *reinterpret_cast<uint2*>(hi);
    *reinterpret_cast<uint2*>(g_xc + base + 32 + pos) = *reinterpret_cast<uint2*>(lo);
}

// ============================================================================
// Pre-pass 2: W [d][i][o] -> combined transposed (hi|lo) layout
// ============================================================================
__global__ void convert_w_kernel(const float* __restrict__ W) {
    __shared__ float tile[32][33];
    int d  = blockIdx.z;
    int o0 = blockIdx.x * 32;
    int i0 = blockIdx.y * 32;
    int tx = threadIdx.x, ty = threadIdx.y;
    tile[ty][tx] = W[((size_t)d * DIN + (i0 + ty)) * DFEAT + (o0 + tx)];
    __syncthreads();
    float f = tile[tx][ty];
    __half hi = __float2half_rn(f);
    __half lo = __float2half_rn(f - __half2float(hi));
    size_t base = (((size_t)d * DFEAT + (o0 + ty)) * NK + (i0 >> 5)) * 64;
    g_wc[base + tx]      = hi;
    g_wc[base + 32 + tx] = lo;
}

__global__ void scale_kernel(const float* __restrict__ lv) {
    g_scale = 0.015625f * expf(0.5f * lv[0]);
}

// ============================================================================
// Main fused kernel: cg2 SS-mode, TMA-fed (rank1 TMA -> rank0 barrier),
// warp-split (warp0 = MMA on rank0, warp1 = prefetch on both ranks).
// ============================================================================
__global__ void __launch_bounds__(128, 1) __cluster_dims__(2, 1, 1)
sketch_kernel(float* __restrict__ out,
              const __grid_constant__ CUtensorMap map_x,
              const __grid_constant__ CUtensorMap map_w) {
#if defined(__CUDA_ARCH_FEAT_SM103_ALL) || defined(__CUDA_ARCH_FEAT_SM100_ALL)
    extern __shared__ char smem[];
    uint32_t sb = smem_u32(smem);
    int tid = threadIdx.x;
    int wid = tid >> 5, lid = tid & 31;
    uint32_t rank;
    asm("mov.u32 %0, %%cluster_ctarank;" : "=r"(rank));
    int nt, mt;
    cl_coords((int)blockIdx.x >> 1, &nt, &mt);
    int n0  = nt * TN;                         // full n tile (epilogue)
    int m0  = mt * TMC + (int)rank * 128;      // this CTA's A/D rows
    int nb0 = n0 + (int)rank * 64;             // this CTA's B half rows

    if (wid == 0) {
        asm volatile("tcgen05.alloc.cta_group::2.sync.aligned.shared::cta.b32 [%0], %1;"
                     :: "r"(sb + OFF_TMEM), "r"((uint32_t)TMEM_COLS) : "memory");
        asm volatile("tcgen05.relinquish_alloc_permit.cta_group::2.sync.aligned;");
    }
    if (tid == 0) {
        #pragma unroll
        for (int s = 0; s < STAGES; s++) {
            asm volatile("mbarrier.init.shared.b64 [%0], %1;"
                         :: "r"(sb + OFF_EMPTY(s)), "r"(1) : "memory");
            asm volatile("mbarrier.init.shared.b64 [%0], %1;"
                         :: "r"(sb + OFF_FULL(s)), "r"(1) : "memory");
        }
        asm volatile("mbarrier.init.shared.b64 [%0], %1;"
                     :: "r"(sb + OFF_MMADONE), "r"(1) : "memory");
    }
    __syncthreads();
    // Barriers on rank0 must be live before ANY TMA targets them.
    asm volatile("barrier.cluster.arrive.aligned;" ::: "memory");
    asm volatile("barrier.cluster.wait.aligned;" ::: "memory");

    uint32_t tmem;
    asm volatile("ld.shared.b32 %0, [%1];" : "=r"(tmem) : "r"(sb + OFF_TMEM));

    #define MBAR_WAIT(addr, parity) do {                                           \
        uint32_t _m = (addr), _p = (parity), _d;                                   \
        asm volatile("{ .reg .pred p; "                                            \
            "mbarrier.try_wait.parity.acquire.cta.shared::cta.b64 p, [%1], %2; "   \
            "selp.b32 %0, 1, 0, p; }" : "=r"(_d) : "r"(_m), "r"(_p) : "memory");   \
        if (!_d) {                                                                 \
            asm volatile("{ .reg .pred P; L_%=: "                                  \
                "mbarrier.try_wait.parity.acquire.cta.shared::cta.b64 P, [%0], %1, 0x989680; " \
                "@P bra.uni D_%=; bra.uni L_%=; D_%=: }"                           \
                :: "r"(_m), "r"(_p) : "memory");                                   \
        }                                                                          \
    } while (0)

    // cg2 TMA: data to local SMEM, complete_tx to the LEADER's barrier (bit24).
    #define TMA_LD_CG2(smemaddr, map, c1, c2, mbar)                                \
        asm volatile("{ .reg .b32 lb; and.b32 lb, %5, 0xFEFFFFFF;"                 \
            "cp.async.bulk.tensor.3d.cta_group::2.shared::cluster.global.tile"     \
            ".mbarrier::complete_tx::bytes [%0], [%1, {%2, %3, %4}], [lb]; }"      \
            :: "r"(smemaddr), "l"(map), "r"(0), "r"(c1), "r"(c2),                  \
               "r"(mbar) : "memory")

    // Issue this CTA's 4 TMA loads for chunk kt (A half + 3 B halves).
    auto tma_stage = [&](int kt) {
        int s = kt & (STAGES - 1);
        uint32_t base = sb + SMEM_TILES + s * STAGE_BYTES;
        uint32_t mbar = sb + OFF_FULL(s);
        TMA_LD_CG2(base, &map_x, kt, m0, mbar);
        #pragma unroll
        for (int d = 0; d < DEG; d++) {
            TMA_LD_CG2(base + KTILE_A + d * KTILE_B, &map_w, kt,
                       d * DFEAT + nb0, mbar);
        }
    };

    constexpr uint64_t DESC_BASE =
        (uint64_t(2) << 61) | (uint64_t(1) << 46) | (uint64_t(64) << 32) | (uint64_t(1) << 16);

    // Prologue: chunks 0..2 in flight (expect on rank0 only; 2x40KB per stage)
    if (tid == 32) {
        if (rank == 0) {
            #pragma unroll
            for (int s = 0; s < STAGES - 1; s++) {
                asm volatile("mbarrier.arrive.expect_tx.shared.b64 _, [%0], %1;"
                             :: "r"(sb + OFF_FULL(s)),
                                "r"((uint32_t)(2 * STAGE_BYTES)) : "memory");
            }
        }
        tma_stage(0);
        tma_stage(1);
        tma_stage(2);
    }

    for (int kt = 0; kt < NK; kt++) {
        // MMA warp (rank0 warp0): wait FULL (local, TMA-fed from both CTAs),
        // issue 18 cg2 SS MMAs, commit-multicast completion to both CTAs.
        if (rank == 0 && wid == 0) {
            uint32_t is_elect;
            asm volatile("{ .reg .pred p; elect.sync _|p, 0xFFFFFFFF; selp.b32 %0, 1, 0, p; }"
                         : "=r"(is_elect));
            if (is_elect) {
                int s = kt & (STAGES - 1);
                MBAR_WAIT(sb + OFF_FULL(s), (kt >> 2) & 1);
                uint32_t stage_base = sb + SMEM_TILES + s * STAGE_BYTES;
                uint64_t ad = DESC_BASE | ((uint64_t)(stage_base >> 4) & 0x3FFF);
                #pragma unroll
                for (int d = 0; d < DEG; d++) {
                    uint32_t bb = stage_base + KTILE_A + d * KTILE_B;
                    uint64_t bd = DESC_BASE | ((uint64_t)(bb >> 4) & 0x3FFF);
                    uint32_t acc_t = tmem + TMEM_ACC(d);
                    #pragma unroll
                    for (int ks = 0; ks < 2; ks++) {
                        uint32_t acc0 = (kt > 0 || ks > 0) ? 1u : 0u;
                        asm volatile(   // hi * hi
                            "{ .reg .pred p; setp.ne.u32 p, %5, 0;"
                            "tcgen05.mma.cta_group::2.kind::f16 [%0], %1, %2, %3, "
                            "{%4,%4,%4,%4,%4,%4,%4,%4}, p; }"
                            :: "r"(acc_t), "l"(ad + ks * 2),
                               "l"(bd + ks * 2), "r"(MMA_IDESC), "r"(0u), "r"(acc0)
                            : "memory");
                        asm volatile(   // lo * hi (A lo half at +64B)
                            "{ .reg .pred p; setp.ne.u32 p, %5, 0;"
                            "tcgen05.mma.cta_group::2.kind::f16 [%0], %1, %2, %3, "
                            "{%4,%4,%4,%4,%4,%4,%4,%4}, p; }"
                            :: "r"(acc_t), "l"(ad + 4 + ks * 2),
                               "l"(bd + ks * 2), "r"(MMA_IDESC), "r"(0u), "r"(1u)
                            : "memory");
                        asm volatile(   // hi * lo (B lo half at +64B)
                            "{ .reg .pred p; setp.ne.u32 p, %5, 0;"
                            "tcgen05.mma.cta_group::2.kind::f16 [%0], %1, %2, %3, "
                            "{%4,%4,%4,%4,%4,%4,%4,%4}, p; }"
                            :: "r"(acc_t), "l"(ad + ks * 2),
                               "l"(bd + 4 + ks * 2), "r"(MMA_IDESC), "r"(0u), "r"(1u)
                            : "memory");
                    }
                }
                uint32_t done_bar = (kt == NK - 1) ? (sb + OFF_MMADONE)
                                                   : (sb + OFF_EMPTY(kt & (STAGES - 1)));
                asm volatile(
                    "tcgen05.commit.cta_group::2.mbarrier::arrive::one.shared::cluster.multicast::cluster.b64 [%0], %1;"
                    :: "r"(done_bar), "h"((uint16_t)0x3) : "memory");
            }
        }

        // Prefetch warp (warp1, both ranks): chunk kt+3 into slot (kt-1)%4,
        // gated on that slot's MMA (kt-1) completion (multicast EMPTY).
        if (tid == 32) {
            int pf = kt + STAGES - 1;
            if (pf < NK) {
                if (kt >= 1) {
                    MBAR_WAIT(sb + OFF_EMPTY((kt - 1) & (STAGES - 1)),
                              ((kt - 1) >> 2) & 1);
                }
                if (rank == 0) {
                    asm volatile("mbarrier.arrive.expect_tx.shared.b64 _, [%0], %1;"
                                 :: "r"(sb + OFF_FULL(pf & (STAGES - 1))),
                                    "r"((uint32_t)(2 * STAGE_BYTES)) : "memory");
                }
                tma_stage(pf);
            }
        }
    }

    // Epilogue: wait all MMAs (multicast MMADONE), product, scale, store.
    MBAR_WAIT(sb + OFF_MMADONE, 0);
    asm volatile("tcgen05.fence::after_thread_sync;" ::: "memory");

    float scale = g_scale;

    #define TC_LD_X32(r, tmem_addr) \
        asm volatile( \
            "tcgen05.ld.sync.aligned.32x32b.x32.b32 " \
            "{%0, %1, %2, %3, %4, %5, %6, %7, " \
            " %8, %9, %10, %11, %12, %13, %14, %15, " \
            " %16, %17, %18, %19, %20, %21, %22, %23, " \
            " %24, %25, %26, %27, %28, %29, %30, %31}, [%32];" \
            : "=r"((r)[0]),  "=r"((r)[1]),  "=r"((r)[2]),  "=r"((r)[3]), \
              "=r"((r)[4]),  "=r"((r)[5]),  "=r"((r)[6]),  "=r"((r)[7]), \
              "=r"((r)[8]),  "=r"((r)[9]),  "=r"((r)[10]), "=r"((r)[11]), \
              "=r"((r)[12]), "=r"((r)[13]), "=r"((r)[14]), "=r"((r)[15]), \
              "=r"((r)[16]), "=r"((r)[17]), "=r"((r)[18]), "=r"((r)[19]), \
              "=r"((r)[20]), "=r"((r)[21]), "=r"((r)[22]), "=r"((r)[23]), \
              "=r"((r)[24]), "=r"((r)[25]), "=r"((r)[26]), "=r"((r)[27]), \
              "=r"((r)[28]), "=r"((r)[29]), "=r"((r)[30]), "=r"((r)[31]) \
            : "r"(tmem_addr))

    float* orow = out + (size_t)(m0 + wid * 32 + lid) * DFEAT + n0;
    #pragma unroll
    for (int c = 0; c < TN / 32; c++) {
        uint32_t r0[32], r1[32], r2[32];
        TC_LD_X32(r0, tmem + TMEM_ACC(0) + c * 32);
        TC_LD_X32(r1, tmem + TMEM_ACC(1) + c * 32);
        TC_LD_X32(r2, tmem + TMEM_ACC(2) + c * 32);
        asm volatile("tcgen05.wait::ld.sync.aligned;" ::: "memory");
        float f[32];
        #pragma unroll
        for (int j = 0; j < 32; j++) {
            f[j] = __uint_as_float(r0[j]) * __uint_as_float(r1[j]) *
                   __uint_as_float(r2[j]) * scale;
        }
        #pragma unroll
        for (int q = 0; q < 8; q++) {
            float4 v = make_float4(f[q * 4], f[q * 4 + 1], f[q * 4 + 2], f[q * 4 + 3]);
            *reinterpret_cast<float4*>(orow + c * 32 + q * 4) = v;
        }
    }

    asm volatile("tcgen05.fence::before_thread_sync;" ::: "memory");
    __syncthreads();
    if (wid == 0) {
        asm volatile("tcgen05.relinquish_alloc_permit.cta_group::2.sync.aligned;");
        asm volatile("tcgen05.dealloc.cta_group::2.sync.aligned.b32 %0, %1;"
                     :: "r"(tmem), "r"((uint32_t)TMEM_COLS));
    }
    // No CTA may exit while its peer might still reference its SMEM/TMEM.
    asm volatile("barrier.cluster.arrive.aligned;" ::: "memory");
    asm volatile("barrier.cluster.wait.aligned;" ::: "memory");
    #undef MBAR_WAIT
    #undef TMA_LD_CG2
    #undef TC_LD_X32

#else
    // ------------------------------------------------------------------
    // Fallback path (base sm_103): cp.async + ldmatrix + mma.sync on the
    // combined layout. Each CTA independently computes its 128x128 tile
    // (rank = bid&1 selects the m-half; no cluster cooperation).
    // ------------------------------------------------------------------
    extern __shared__ char smem[];
    uint32_t sb = smem_u32(smem);
    int tid  = threadIdx.x;
    int wid  = tid >> 5;
    int lane = tid & 31;
    int nt, mt;
    cl_coords((int)blockIdx.x >> 1, &nt, &mt);
    int n0 = nt * TN;
    int m0 = mt * TMC + (int)(blockIdx.x & 1) * 128;

    float scale = g_scale;

    auto load_stage_fb = [&](int s, int kt, int p) {
        uint32_t base = sb + SMEM_TILES + s * STAGE_BYTES;
        #pragma unroll
        for (int c = tid; c < 1024; c += 128) {
            int row = c >> 3, ch = c & 7;
            uint32_t off = (uint32_t)(row << 7) | (uint32_t)(ch << 4);
            const __half* src = g_xc + ((size_t)(m0 + row) * NK + kt) * 64 + ch * 8;
            CP_ASYNC16(base + SWZ128(off), src);
        }
        #pragma unroll
        for (int d = 0; d < DEG; d++) {
            uint32_t tb = base + KTILE_A + d * KTILE_B;
            #pragma unroll
            for (int j = 0; j < 2; j++) {
                int c = tid + 128 * j;
                int row = c >> 3, ch = c & 7;
                uint32_t off = (uint32_t)(row << 7) | (uint32_t)(ch << 4);
                const __half* src = g_wc +
                    (((size_t)d * DFEAT + n0 + 32 * p + row) * NK + kt) * 64 + ch * 8;
                CP_ASYNC16(tb + SWZ128(off), src);
            }
        }
    };

    int lr = lane & 15;
    int lc = lane >> 4;

    for (int p = 0; p < 4; p++) {
        float acc[DEG][2][4][4];
        #pragma unroll
        for (int d = 0; d < DEG; d++)
            #pragma unroll
            for (int mtl = 0; mtl < 2; mtl++)
                #pragma unroll
                for (int ntl = 0; ntl < 4; ntl++)
                    #pragma unroll
                    for (int r = 0; r < 4; r++) acc[d][mtl][ntl][r] = 0.0f;

        #pragma unroll
        for (int s = 0; s < 2; s++) {
            load_stage_fb(s, s, p);
            CP_COMMIT();
        }

        for (int kt = 0; kt < NK; kt++) {
            CP_WAIT(1);
            __syncthreads();
            int s = kt % 3;
            // note: use 3-slot rotation within 4-slot space
            uint32_t abase = sb + SMEM_TILES + s * STAGE_BYTES;

            #pragma unroll
            for (int ks = 0; ks < 2; ks++) {
                uint32_t a_hi[2][4], a_lo[2][4];
                #pragma unroll
                for (int mtl = 0; mtl < 2; mtl++) {
                    uint32_t row = 32 * wid + 16 * mtl + lr;
                    uint32_t byt = (uint32_t)(ks * 32 + lc * 16);
                    uint32_t addr_h = abase + SWZ128((row << 7) | byt);
                    uint32_t addr_l = abase + SWZ128((row << 7) | (64 + byt));
                    asm volatile(
                        "ldmatrix.sync.aligned.m8n8.x4.shared.b16 {%0,%1,%2,%3}, [%4];"
                        : "=r"(a_hi[mtl][0]), "=r"(a_hi[mtl][1]), "=r"(a_hi[mtl][2]), "=r"(a_hi[mtl][3])
                        : "r"(addr_h));
                    asm volatile(
                        "ldmatrix.sync.aligned.m8n8.x4.shared.b16 {%0,%1,%2,%3}, [%4];"
                        : "=r"(a_lo[mtl][0]), "=r"(a_lo[mtl][1]), "=r"(a_lo[mtl][2]), "=r"(a_lo[mtl][3])
                        : "r"(addr_l));
                }
                #pragma unroll
                for (int d = 0; d < DEG; d++) {
                    uint32_t bbase = abase + KTILE_A + d * KTILE_B;
                    uint32_t b_hi[2][4], b_lo[2][4];
                    #pragma unroll
                    for (int h = 0; h < 2; h++) {
                        uint32_t row = 16 * h + lr;
                        uint32_t byt = (uint32_t)(ks * 32 + lc * 16);
                        uint32_t addr_h = bbase + SWZ128((row << 7) | byt);
                        uint32_t addr_l = bbase + SWZ128((row << 7) | (64 + byt));
                        asm volatile(
                            "ldmatrix.sync.aligned.m8n8.x4.shared.b16 {%0,%1,%2,%3}, [%4];"
                            : "=r"(b_hi[h][0]), "=r"(b_hi[h][1]), "=r"(b_hi[h][2]), "=r"(b_hi[h][3])
                            : "r"(addr_h));
                        asm volatile(
                            "ldmatrix.sync.aligned.m8n8.x4.shared.b16 {%0,%1,%2,%3}, [%4];"
                            : "=r"(b_lo[h][0]), "=r"(b_lo[h][1]), "=r"(b_lo[h][2]), "=r"(b_lo[h][3])
                            : "r"(addr_l));
                    }
                    #pragma unroll
                    for (int mtl = 0; mtl < 2; mtl++) {
                        #pragma unroll
                        for (int ntl = 0; ntl < 4; ntl++) {
                            int h = ntl >> 1, lo = ntl & 1;
                            float* c = acc[d][mtl][ntl];
                            asm volatile(
                                "mma.sync.aligned.m16n8k16.row.col.f32.f16.f16.f32 "
                                "{%0,%1,%2,%3}, {%4,%5,%6,%7}, {%8,%9}, {%0,%1,%2,%3};"
                                : "+f"(c[0]), "+f"(c[1]), "+f"(c[2]), "+f"(c[3])
                                : "r"(a_hi[mtl][0]), "r"(a_hi[mtl][1]), "r"(a_hi[mtl][2]), "r"(a_hi[mtl][3]),
                                  "r"(b_hi[h][lo]), "r"(b_hi[h][lo + 2]));
                            asm volatile(
                                "mma.sync.aligned.m16n8k16.row.col.f32.f16.f16.f32 "
                                "{%0,%1,%2,%3}, {%4,%5,%6,%7}, {%8,%9}, {%0,%1,%2,%3};"
                                : "+f"(c[0]), "+f"(c[1]), "+f"(c[2]), "+f"(c[3])
                                : "r"(a_lo[mtl][0]), "r"(a_lo[mtl][1]), "r"(a_lo[mtl][2]), "r"(a_lo[mtl][3]),
                                  "r"(b_hi[h][lo]), "r"(b_hi[h][lo + 2]));
                            asm volatile(
                                "mma.sync.aligned.m16n8k16.row.col.f32.f16.f16.f32 "
                                "{%0,%1,%2,%3}, {%4,%5,%6,%7}, {%8,%9}, {%0,%1,%2,%3};"
                                : "+f"(c[0]), "+f"(c[1]), "+f"(c[2]), "+f"(c[3])
                                : "r"(a_hi[mtl][0]), "r"(a_hi[mtl][1]), "r"(a_hi[mtl][2]), "r"(a_hi[mtl][3]),
                                  "r"(b_lo[h][lo]), "r"(b_lo[h][lo + 2]));
                        }
                    }
                }
            }
            __syncthreads();
            int nk = kt + 2;
            if (nk < NK) load_stage_fb(nk % 3, nk, p);
            CP_COMMIT();
        }
        CP_WAIT(0);
        __syncthreads();

        int g = lane >> 2, t = lane & 3;
        #pragma unroll
        for (int mtl = 0; mtl < 2; mtl++) {
            #pragma unroll
            for (int ntl = 0; ntl < 4; ntl++) {
                int row = m0 + 32 * wid + 16 * mtl + g;
                int col = n0 + 32 * p + 8 * ntl + 2 * t;
                float p0 = acc[0][mtl][ntl][0] * acc[1][mtl][ntl][0] * acc[2][mtl][ntl][0] * scale;
                float p1 = acc[0][mtl][ntl][1] * acc[1][mtl][ntl][1] * acc[2][mtl][ntl][1] * scale;
                float p2 = acc[0][mtl][ntl][2] * acc[1][mtl][ntl][2] * acc[2][mtl][ntl][2] * scale;
                float p3 = acc[0][mtl][ntl][3] * acc[1][mtl][ntl][3] * acc[2][mtl][ntl][3] * scale;
                *reinterpret_cast<float2*>(out + (size_t)row * DFEAT + col) =
                    make_float2(p0, p1);
                *reinterpret_cast<float2*>(out + (size_t)(row + 8) * DFEAT + col) =
                    make_float2(p2, p3);
            }
        }
    }
#endif
}

// ============================================================================
// Launch: encode tensormaps via driver entry point (no -lcuda link needed)
// ============================================================================
typedef CUresult (*PFN_EncodeTiled)(
    CUtensorMap*, CUtensorMapDataType, cuuint32_t, void*,
    const cuuint64_t*, const cuuint64_t*, const cuuint32_t*, const cuuint32_t*,
    CUtensorMapInterleave, CUtensorMapSwizzle, CUtensorMapL2promotion,
    CUtensorMapFloatOOBfill);

extern "C" void kernel_launch(void* const* d_in, const int* in_sizes, int n_in,
                              void* d_out, int out_size) {
    const float* x   = (const float*)d_in[0];
    const float* W   = (const float*)d_in[1];
    const float* lls = (const float*)d_in[2];
    const float* lv  = (const float*)d_in[3];
    float* out = (float*)d_out;

    convert_x_kernel<<<(BATCH * (size_t)DIN) / (4 * 256), 256>>>(x, lls);
    convert_w_kernel<<<dim3(DFEAT / 32, DIN / 32, DEG), dim3(32, 32)>>>(W);
    scale_kernel<<<1, 1>>>(lv);

    PFN_EncodeTiled encode = nullptr;
    cudaDriverEntryPointQueryResult qr;
    cudaGetDriverEntryPoint("cuTensorMapEncodeTiled", (void**)&encode,
                            cudaEnableDefault, &qr);

    void *p_xc = nullptr, *p_wc = nullptr;
    cudaGetSymbolAddress(&p_xc, g_xc);
    cudaGetSymbolAddress(&p_wc, g_wc);

    CUtensorMap map_x{}, map_w{};
    {
        cuuint64_t dims[3]    = {64, NK, BATCH};
        cuuint64_t strides[2] = {128, 128ull * NK};
        cuuint32_t box[3]     = {64, 1, 128};          // A half: 128 rows
        cuuint32_t es[3]      = {1, 1, 1};
        encode(&map_x, CU_TENSOR_MAP_DATA_TYPE_FLOAT16, 3, p_xc,
               dims, strides, box, es,
               CU_TENSOR_MAP_INTERLEAVE_NONE, CU_TENSOR_MAP_SWIZZLE_128B,
               CU_TENSOR_MAP_L2_PROMOTION_L2_128B,
               CU_TENSOR_MAP_FLOAT_OOB_FILL_NONE);
    }
    {
        cuuint64_t dims[3]    = {64, NK, (cuuint64_t)DEG * DFEAT};
        cuuint64_t strides[2] = {128, 128ull * NK};
        cuuint32_t box[3]     = {64, 1, 64};           // B half: 64 rows
        cuuint32_t es[3]      = {1, 1, 1};
        encode(&map_w, CU_TENSOR_MAP_DATA_TYPE_FLOAT16, 3, p_wc,
               dims, strides, box, es,
               CU_TENSOR_MAP_INTERLEAVE_NONE, CU_TENSOR_MAP_SWIZZLE_128B,
               CU_TENSOR_MAP_L2_PROMOTION_L2_128B,
               CU_TENSOR_MAP_FLOAT_OOB_FILL_NONE);
    }

    cudaFuncSetAttribute(sketch_kernel,
                         cudaFuncAttributeMaxDynamicSharedMemorySize, SMEM_TOTAL);
    // 4096 CTAs = 2048 clusters of 2 (rank = bid & 1)
    sketch_kernel<<<2 * NTILES_N * NTILES_M, 128, SMEM_TOTAL>>>(out, map_x, map_w);
}

// round 14
// speedup vs baseline: 1.6216x; 1.0185x over previous
#include <cuda_runtime.h>
#include <cuda.h>
#include <cuda_fp16.h>
#include <cstdint>
#include <cmath>

// ============================================================================
// Problem constants
// ============================================================================
#define BATCH  16384
#define DIN    1024
#define DFEAT  4096
#define DEG    3

// cg2 tiling: 2-CTA cluster computes 256(m) x 128(n); persistent clusters.
#define TMC 256
#define TN  128
#define BK  32         // 32 halves; combined row = [hi 64B | lo 64B] = 128B
#define NK  (DIN / BK) // 32 K-chunks
#define STAGES 4

#define NTILES_N (DFEAT / TN)     // 32
#define NTILES_M (BATCH / TMC)    // 64
#define TOTAL_CL (NTILES_N * NTILES_M)   // 2048
#define NBAND    8
#define GRID_CTAS 148             // 74 persistent clusters (<=1 wave on 148/152 SM)

#define KTILE_A  16384
#define KTILE_B  8192
#define STAGE_BYTES (KTILE_A + DEG * KTILE_B)   // 40960
#define SMEM_TILES  1024
#define SMEM_TOTAL  (SMEM_TILES + STAGES * STAGE_BYTES)   // 164864

// SMEM control offsets
#define OFF_TMEM     0
#define OFF_EMPTY(s) (16 + 8 * (s))
#define OFF_MMADONE  56
#define OFF_FULL(s)  (64 + 8 * (s))
#define OFF_ACCFREE  96

// TMEM: 3 fp32 accumulators x 128 cols per CTA
#define TMEM_ACC(d) ((d) * 128)
#define TMEM_COLS 512

static constexpr uint32_t MMA_IDESC =
    (1u << 4) | ((TN / 8) << 17) | ((TMC / 16) << 24);

// ============================================================================
// Scratch: combined interleaved fp16 pairs (row = [hi 32 | lo 32] halves).
// ============================================================================
__device__ __half g_xc[(size_t)BATCH * NK * 64];
__device__ __half g_wc[(size_t)DEG * DFEAT * NK * 64];
__device__ float  g_scale;

// ============================================================================
// Helpers
// ============================================================================
__device__ __forceinline__ uint32_t smem_u32(const void* p) {
    uint32_t a;
    asm("{ .reg .u64 t; cvta.to.shared.u64 t, %1; cvt.u32.u64 %0, t; }"
        : "=r"(a) : "l"(p));
    return a;
}

#define CP_ASYNC16(dst, src) \
    asm volatile("cp.async.cg.shared.global [%0], [%1], 16;" \
                 :: "r"(dst), "l"(src) : "memory")
#define CP_COMMIT() asm volatile("cp.async.commit_group;" ::: "memory")
#define CP_WAIT(n)  asm volatile("cp.async.wait_group %0;" :: "n"(n) : "memory")

#define SWZ128(off) ((off) ^ (((off) >> 3) & 0x70))

// Cluster raster: band of NBAND n-tiles, m-major inside the band.
__device__ __forceinline__ void cl_coords(int cl, int* nt, int* mt) {
    int band = cl / (NBAND * NTILES_M);
    int r    = cl % (NBAND * NTILES_M);
    *nt = band * NBAND + (r % NBAND);
    *mt = r / NBAND;
}

// ============================================================================
// Pre-pass 1: x -> combined (hi|lo) layout, scaled by exp(-ll)
// ============================================================================
__global__ void convert_x_kernel(const float* __restrict__ x,
                                 const float* __restrict__ lls) {
    float s = expf(-lls[0]);
    size_t e = ((size_t)blockIdx.x * blockDim.x + threadIdx.x) * 4;
    float4 v = *reinterpret_cast<const float4*>(x + e);
    float f[4] = {v.x * s, v.y * s, v.z * s, v.w * s};
    __half hi[4], lo[4];
    #pragma unroll
    for (int j = 0; j < 4; j++) {
        hi[j] = __float2half_rn(f[j]);
        lo[j] = __float2half_rn(f[j] - __half2float(hi[j]));
    }
    size_t m = e >> 10;
    int    k = (int)(e & 1023);
    int    c = k >> 5, pos = k & 31;
    size_t base = ((size_t)m * NK + c) * 64;
    *reinterpret_cast<uint2*>(g_xc + base + pos)      = *reinterpret_cast<uint2*>(hi);
    *reinterpret_cast<uint2*>(g_xc + base + 32 + pos) = *reinterpret_cast<uint2*>(lo);
}

// ============================================================================
// Pre-pass 2: W [d][i][o] -> combined transposed (hi|lo) layout
// ============================================================================
__global__ void convert_w_kernel(const float* __restrict__ W) {
    __shared__ float tile[32][33];
    int d  = blockIdx.z;
    int o0 = blockIdx.x * 32;
    int i0 = blockIdx.y * 32;
    int tx = threadIdx.x, ty = threadIdx.y;
    tile[ty][tx] = W[((size_t)d * DIN + (i0 + ty)) * DFEAT + (o0 + tx)];
    __syncthreads();
    float f = tile[tx][ty];
    __half hi = __float2half_rn(f);
    __half lo = __float2half_rn(f - __half2float(hi));
    size_t base = (((size_t)d * DFEAT + (o0 + ty)) * NK + (i0 >> 5)) * 64;
    g_wc[base + tx]      = hi;
    g_wc[base + 32 + tx] = lo;
}

__global__ void scale_kernel(const float* __restrict__ lv) {
    g_scale = 0.015625f * expf(0.5f * lv[0]);
}

// ============================================================================
// Main fused kernel: PERSISTENT cg2 SS-mode, TMA-fed, warp-split.
// Continuous chunk index q = tloc*32 + kt: slot q&3, parity (q>>2)&1.
// ============================================================================
__global__ void __launch_bounds__(128, 1) __cluster_dims__(2, 1, 1)
sketch_kernel(float* __restrict__ out,
              const __grid_constant__ CUtensorMap map_x,
              const __grid_constant__ CUtensorMap map_w) {
#if defined(__CUDA_ARCH_FEAT_SM103_ALL) || defined(__CUDA_ARCH_FEAT_SM100_ALL)
    extern __shared__ char smem[];
    uint32_t sb = smem_u32(smem);
    int tid = threadIdx.x;
    int wid = tid >> 5, lid = tid & 31;
    uint32_t rank;
    asm("mov.u32 %0, %%cluster_ctarank;" : "=r"(rank));
    int cl0 = (int)blockIdx.x >> 1;
    int ncl = GRID_CTAS >> 1;     // 74 persistent clusters

    if (wid == 0) {
        asm volatile("tcgen05.alloc.cta_group::2.sync.aligned.shared::cta.b32 [%0], %1;"
                     :: "r"(sb + OFF_TMEM), "r"((uint32_t)TMEM_COLS) : "memory");
        asm volatile("tcgen05.relinquish_alloc_permit.cta_group::2.sync.aligned;");
    }
    if (tid == 0) {
        #pragma unroll
        for (int s = 0; s < STAGES; s++) {
            asm volatile("mbarrier.init.shared.b64 [%0], %1;"
                         :: "r"(sb + OFF_EMPTY(s)), "r"(1) : "memory");
            asm volatile("mbarrier.init.shared.b64 [%0], %1;"
                         :: "r"(sb + OFF_FULL(s)), "r"(1) : "memory");
        }
        asm volatile("mbarrier.init.shared.b64 [%0], %1;"
                     :: "r"(sb + OFF_MMADONE), "r"(1) : "memory");
        asm volatile("mbarrier.init.shared.b64 [%0], %1;"
                     :: "r"(sb + OFF_ACCFREE), "r"(1) : "memory");
    }
    __syncthreads();
    asm volatile("barrier.cluster.arrive.aligned;" ::: "memory");
    asm volatile("barrier.cluster.wait.aligned;" ::: "memory");

    uint32_t tmem;
    asm volatile("ld.shared.b32 %0, [%1];" : "=r"(tmem) : "r"(sb + OFF_TMEM));

    #define MBAR_WAIT(addr, parity) do {                                           \
        uint32_t _m = (addr), _p = (parity), _d;                                   \
        asm volatile("{ .reg .pred p; "                                            \
            "mbarrier.try_wait.parity.acquire.cta.shared::cta.b64 p, [%1], %2; "   \
            "selp.b32 %0, 1, 0, p; }" : "=r"(_d) : "r"(_m), "r"(_p) : "memory");   \
        if (!_d) {                                                                 \
            asm volatile("{ .reg .pred P; L_%=: "                                  \
                "mbarrier.try_wait.parity.acquire.cta.shared::cta.b64 P, [%0], %1, 0x989680; " \
                "@P bra.uni D_%=; bra.uni L_%=; D_%=: }"                           \
                :: "r"(_m), "r"(_p) : "memory");                                   \
        }                                                                          \
    } while (0)

    #define MBAR_WAIT_CL(addr, parity) do {                                        \
        uint32_t _m = (addr), _p = (parity), _d;                                   \
        asm volatile("{ .reg .pred p; "                                            \
            "mbarrier.try_wait.parity.acquire.cluster.shared::cta.b64 p, [%1], %2; " \
            "selp.b32 %0, 1, 0, p; }" : "=r"(_d) : "r"(_m), "r"(_p) : "memory");   \
        if (!_d) {                                                                 \
            asm volatile("{ .reg .pred P; L_%=: "                                  \
                "mbarrier.try_wait.parity.acquire.cluster.shared::cta.b64 P, [%0], %1, 0x989680; " \
                "@P bra.uni D_%=; bra.uni L_%=; D_%=: }"                           \
                :: "r"(_m), "r"(_p) : "memory");                                   \
        }                                                                          \
    } while (0)

    #define TMA_LD_CG2(smemaddr, map, c1, c2, mbar)                                \
        asm volatile("{ .reg .b32 lb; and.b32 lb, %5, 0xFEFFFFFF;"                 \
            "cp.async.bulk.tensor.3d.cta_group::2.shared::cluster.global.tile"     \
            ".mbarrier::complete_tx::bytes [%0], [%1, {%2, %3, %4}], [lb]; }"      \
            :: "r"(smemaddr), "l"(map), "r"(0), "r"(c1), "r"(c2),                  \
               "r"(mbar) : "memory")

    // Issue this CTA's 4 TMA loads for tile `pcl`, chunk `pfk`, slot `slot`.
    auto tma_stage = [&](int pcl, int pfk, int slot) {
        int nt, mt;
        cl_coords(pcl, &nt, &mt);
        int pm0  = mt * TMC + (int)rank * 128;
        int pnb0 = nt * TN + (int)rank * 64;
        uint32_t base = sb + SMEM_TILES + slot * STAGE_BYTES;
        uint32_t mbar = sb + OFF_FULL(slot);
        TMA_LD_CG2(base, &map_x, pfk, pm0, mbar);
        #pragma unroll
        for (int d = 0; d < DEG; d++) {
            TMA_LD_CG2(base + KTILE_A + d * KTILE_B, &map_w, pfk,
                       d * DFEAT + pnb0, mbar);
        }
    };

    constexpr uint64_t DESC_BASE =
        (uint64_t(2) << 61) | (uint64_t(1) << 46) | (uint64_t(64) << 32) | (uint64_t(1) << 16);

    #define TC_LD_X32(r, tmem_addr) \
        asm volatile( \
            "tcgen05.ld.sync.aligned.32x32b.x32.b32 " \
            "{%0, %1, %2, %3, %4, %5, %6, %7, " \
            " %8, %9, %10, %11, %12, %13, %14, %15, " \
            " %16, %17, %18, %19, %20, %21, %22, %23, " \
            " %24, %25, %26, %27, %28, %29, %30, %31}, [%32];" \
            : "=r"((r)[0]),  "=r"((r)[1]),  "=r"((r)[2]),  "=r"((r)[3]), \
              "=r"((r)[4]),  "=r"((r)[5]),  "=r"((r)[6]),  "=r"((r)[7]), \
              "=r"((r)[8]),  "=r"((r)[9]),  "=r"((r)[10]), "=r"((r)[11]), \
              "=r"((r)[12]), "=r"((r)[13]), "=r"((r)[14]), "=r"((r)[15]), \
              "=r"((r)[16]), "=r"((r)[17]), "=r"((r)[18]), "=r"((r)[19]), \
              "=r"((r)[20]), "=r"((r)[21]), "=r"((r)[22]), "=r"((r)[23]), \
              "=r"((r)[24]), "=r"((r)[25]), "=r"((r)[26]), "=r"((r)[27]), \
              "=r"((r)[28]), "=r"((r)[29]), "=r"((r)[30]), "=r"((r)[31]) \
            : "r"(tmem_addr))

    float scale = g_scale;

    // Warp1 prologue: chunks 0,1,2 of the first tile.
    if (tid == 32 && cl0 < TOTAL_CL) {
        #pragma unroll
        for (int c = 0; c < STAGES - 1; c++) {
            if (rank == 0) {
                asm volatile("mbarrier.arrive.expect_tx.shared.b64 _, [%0], %1;"
                             :: "r"(sb + OFF_FULL(c)),
                                "r"((uint32_t)(2 * STAGE_BYTES)) : "memory");
            }
            tma_stage(cl0, c, c);
        }
    }

    int tloc = 0;
    for (int cl = cl0; cl < TOTAL_CL; cl += ncl, tloc++) {
        int nt, mt;
        cl_coords(cl, &nt, &mt);
        int n0 = nt * TN;
        int m0 = mt * TMC + (int)rank * 128;

        for (int kt = 0; kt < NK; kt++) {
            int qg = tloc * NK + kt;      // continuous chunk index
            int s  = qg & (STAGES - 1);

            // MMA warp (rank0 warp0)
            if (rank == 0 && wid == 0) {
                uint32_t is_elect;
                asm volatile("{ .reg .pred p; elect.sync _|p, 0xFFFFFFFF; selp.b32 %0, 1, 0, p; }"
                             : "=r"(is_elect));
                if (is_elect) {
                    if (kt == 0 && tloc >= 1) {
                        // rank1's epilogue of previous tile must be done
                        MBAR_WAIT_CL(sb + OFF_ACCFREE, (tloc - 1) & 1);
                        asm volatile("tcgen05.fence::after_thread_sync;" ::: "memory");
                    }
                    MBAR_WAIT(sb + OFF_FULL(s), (qg >> 2) & 1);
                    uint32_t stage_base = sb + SMEM_TILES + s * STAGE_BYTES;
                    uint64_t ad = DESC_BASE | ((uint64_t)(stage_base >> 4) & 0x3FFF);
                    #pragma unroll
                    for (int d = 0; d < DEG; d++) {
                        uint32_t bb = stage_base + KTILE_A + d * KTILE_B;
                        uint64_t bd = DESC_BASE | ((uint64_t)(bb >> 4) & 0x3FFF);
                        uint32_t acc_t = tmem + TMEM_ACC(d);
                        #pragma unroll
                        for (int ks = 0; ks < 2; ks++) {
                            uint32_t acc0 = (kt > 0 || ks > 0) ? 1u : 0u;
                            asm volatile(   // hi * hi
                                "{ .reg .pred p; setp.ne.u32 p, %5, 0;"
                                "tcgen05.mma.cta_group::2.kind::f16 [%0], %1, %2, %3, "
                                "{%4,%4,%4,%4,%4,%4,%4,%4}, p; }"
                                :: "r"(acc_t), "l"(ad + ks * 2),
                                   "l"(bd + ks * 2), "r"(MMA_IDESC), "r"(0u), "r"(acc0)
                                : "memory");
                            asm volatile(   // lo * hi (A lo half at +64B)
                                "{ .reg .pred p; setp.ne.u32 p, %5, 0;"
                                "tcgen05.mma.cta_group::2.kind::f16 [%0], %1, %2, %3, "
                                "{%4,%4,%4,%4,%4,%4,%4,%4}, p; }"
                                :: "r"(acc_t), "l"(ad + 4 + ks * 2),
                                   "l"(bd + ks * 2), "r"(MMA_IDESC), "r"(0u), "r"(1u)
                                : "memory");
                            asm volatile(   // hi * lo (B lo half at +64B)
                                "{ .reg .pred p; setp.ne.u32 p, %5, 0;"
                                "tcgen05.mma.cta_group::2.kind::f16 [%0], %1, %2, %3, "
                                "{%4,%4,%4,%4,%4,%4,%4,%4}, p; }"
                                :: "r"(acc_t), "l"(ad + ks * 2),
                                   "l"(bd + 4 + ks * 2), "r"(MMA_IDESC), "r"(0u), "r"(1u)
                                : "memory");
                        }
                    }
                    // Keep the EMPTY chain alive every chunk; additionally
                    // signal MMADONE at tile end (second commit, same MMA set).
                    asm volatile(
                        "tcgen05.commit.cta_group::2.mbarrier::arrive::one.shared::cluster.multicast::cluster.b64 [%0], %1;"
                        :: "r"(sb + OFF_EMPTY(s)), "h"((uint16_t)0x3) : "memory");
                    if (kt == NK - 1) {
                        asm volatile(
                            "tcgen05.commit.cta_group::2.mbarrier::arrive::one.shared::cluster.multicast::cluster.b64 [%0], %1;"
                            :: "r"(sb + OFF_MMADONE), "h"((uint16_t)0x3) : "memory");
                    }
                }
            }

            // Prefetch warp (tid 32, both ranks): chunk qg+3 (may belong to
            // the NEXT tile), gated on EMPTY of chunk qg-1's slot.
            if (tid == 32) {
                int pfg = qg + STAGES - 1;
                int pft = pfg >> 5;                 // tile-local index
                int pcl = cl0 + pft * ncl;
                if (pcl < TOTAL_CL) {
                    if (qg >= 1) {
                        MBAR_WAIT(sb + OFF_EMPTY((qg - 1) & (STAGES - 1)),
                                  ((qg - 1) >> 2) & 1);
                    }
                    if (rank == 0) {
                        asm volatile("mbarrier.arrive.expect_tx.shared.b64 _, [%0], %1;"
                                     :: "r"(sb + OFF_FULL(pfg & (STAGES - 1))),
                                        "r"((uint32_t)(2 * STAGE_BYTES)) : "memory");
                    }
                    tma_stage(pcl, pfg & 31, pfg & (STAGES - 1));
                }
            }
        }

        // --- Per-tile epilogue (overlaps with next tile's TMA loads) ---
        MBAR_WAIT(sb + OFF_MMADONE, tloc & 1);
        asm volatile("tcgen05.fence::after_thread_sync;" ::: "memory");

        float* orow = out + (size_t)(m0 + wid * 32 + lid) * DFEAT + n0;
        #pragma unroll
        for (int c = 0; c < TN / 32; c++) {
            uint32_t r0[32], r1[32], r2[32];
            TC_LD_X32(r0, tmem + TMEM_ACC(0) + c * 32);
            TC_LD_X32(r1, tmem + TMEM_ACC(1) + c * 32);
            TC_LD_X32(r2, tmem + TMEM_ACC(2) + c * 32);
            asm volatile("tcgen05.wait::ld.sync.aligned;" ::: "memory");
            float f[32];
            #pragma unroll
            for (int j = 0; j < 32; j++) {
                f[j] = __uint_as_float(r0[j]) * __uint_as_float(r1[j]) *
                       __uint_as_float(r2[j]) * scale;
            }
            #pragma unroll
            for (int q = 0; q < 8; q++) {
                float4 v = make_float4(f[q * 4], f[q * 4 + 1], f[q * 4 + 2], f[q * 4 + 3]);
                *reinterpret_cast<float4*>(orow + c * 32 + q * 4) = v;
            }
        }
        asm volatile("tcgen05.fence::before_thread_sync;" ::: "memory");
        __syncthreads();   // all local warps' TMEM reads complete

        // rank1 signals its epilogue completion to rank0's ACCFREE.
        if (rank == 1 && tid == 0) {
            asm volatile("{ .reg .b32 r; mapa.shared::cluster.u32 r, %0, 0;"
                         "mbarrier.arrive.release.cluster.shared::cluster.b64 _, [r]; }"
                         :: "r"(sb + OFF_ACCFREE) : "memory");
        }
    }

    __syncthreads();
    if (wid == 0) {
        asm volatile("tcgen05.dealloc.cta_group::2.sync.aligned.b32 %0, %1;"
                     :: "r"(tmem), "r"((uint32_t)TMEM_COLS));
    }
    asm volatile("barrier.cluster.arrive.aligned;" ::: "memory");
    asm volatile("barrier.cluster.wait.aligned;" ::: "memory");
    #undef MBAR_WAIT
    #undef MBAR_WAIT_CL
    #undef TMA_LD_CG2
    #undef TC_LD_X32

#else
    // ------------------------------------------------------------------
    // Fallback (base sm_103): persistent loop, cp.async + ldmatrix +
    // mma.sync on the combined layout; each CTA does its 128x128 tile.
    // ------------------------------------------------------------------
    extern __shared__ char smem[];
    uint32_t sb = smem_u32(smem);
    int tid  = threadIdx.x;
    int wid  = tid >> 5;
    int lane = tid & 31;
    int cl0 = (int)blockIdx.x >> 1;
    int ncl = GRID_CTAS >> 1;
    int half = (int)(blockIdx.x & 1);

    float scale = g_scale;
    int lr = lane & 15;
    int lc = lane >> 4;

    for (int cl = cl0; cl < TOTAL_CL; cl += ncl) {
        int nt, mt;
        cl_coords(cl, &nt, &mt);
        int n0 = nt * TN;
        int m0 = mt * TMC + half * 128;

        auto load_stage_fb = [&](int s, int kt, int p) {
            uint32_t base = sb + SMEM_TILES + s * STAGE_BYTES;
            #pragma unroll
            for (int c = tid; c < 1024; c += 128) {
                int row = c >> 3, ch = c & 7;
                uint32_t off = (uint32_t)(row << 7) | (uint32_t)(ch << 4);
                const __half* src = g_xc + ((size_t)(m0 + row) * NK + kt) * 64 + ch * 8;
                CP_ASYNC16(base + SWZ128(off), src);
            }
            #pragma unroll
            for (int d = 0; d < DEG; d++) {
                uint32_t tb = base + KTILE_A + d * KTILE_B;
                #pragma unroll
                for (int j = 0; j < 2; j++) {
                    int c = tid + 128 * j;
                    int row = c >> 3, ch = c & 7;
                    uint32_t off = (uint32_t)(row << 7) | (uint32_t)(ch << 4);
                    const __half* src = g_wc +
                        (((size_t)d * DFEAT + n0 + 32 * p + row) * NK + kt) * 64 + ch * 8;
                    CP_ASYNC16(tb + SWZ128(off), src);
                }
            }
        };

        for (int p = 0; p < 4; p++) {
            float acc[DEG][2][4][4];
            #pragma unroll
            for (int d = 0; d < DEG; d++)
                #pragma unroll
                for (int a1 = 0; a1 < 2; a1++)
                    #pragma unroll
                    for (int a2 = 0; a2 < 4; a2++)
                        #pragma unroll
                        for (int r = 0; r < 4; r++) acc[d][a1][a2][r] = 0.0f;

            #pragma unroll
            for (int s = 0; s < 2; s++) {
                load_stage_fb(s, s, p);
                CP_COMMIT();
            }

            for (int kt = 0; kt < NK; kt++) {
                CP_WAIT(1);
                __syncthreads();
                int s = kt % 3;
                uint32_t abase = sb + SMEM_TILES + s * STAGE_BYTES;

                #pragma unroll
                for (int ks = 0; ks < 2; ks++) {
                    uint32_t a_hi[2][4], a_lo[2][4];
                    #pragma unroll
                    for (int a1 = 0; a1 < 2; a1++) {
                        uint32_t row = 32 * wid + 16 * a1 + lr;
                        uint32_t byt = (uint32_t)(ks * 32 + lc * 16);
                        uint32_t addr_h = abase + SWZ128((row << 7) | byt);
                        uint32_t addr_l = abase + SWZ128((row << 7) | (64 + byt));
                        asm volatile(
                            "ldmatrix.sync.aligned.m8n8.x4.shared.b16 {%0,%1,%2,%3}, [%4];"
                            : "=r"(a_hi[a1][0]), "=r"(a_hi[a1][1]), "=r"(a_hi[a1][2]), "=r"(a_hi[a1][3])
                            : "r"(addr_h));
                        asm volatile(
                            "ldmatrix.sync.aligned.m8n8.x4.shared.b16 {%0,%1,%2,%3}, [%4];"
                            : "=r"(a_lo[a1][0]), "=r"(a_lo[a1][1]), "=r"(a_lo[a1][2]), "=r"(a_lo[a1][3])
                            : "r"(addr_l));
                    }
                    #pragma unroll
                    for (int d = 0; d < DEG; d++) {
                        uint32_t bbase = abase + KTILE_A + d * KTILE_B;
                        uint32_t b_hi[2][4], b_lo[2][4];
                        #pragma unroll
                        for (int h = 0; h < 2; h++) {
                            uint32_t row = 16 * h + lr;
                            uint32_t byt = (uint32_t)(ks * 32 + lc * 16);
                            uint32_t addr_h = bbase + SWZ128((row << 7) | byt);
                            uint32_t addr_l = bbase + SWZ128((row << 7) | (64 + byt));
                            asm volatile(
                                "ldmatrix.sync.aligned.m8n8.x4.shared.b16 {%0,%1,%2,%3}, [%4];"
                                : "=r"(b_hi[h][0]), "=r"(b_hi[h][1]), "=r"(b_hi[h][2]), "=r"(b_hi[h][3])
                                : "r"(addr_h));
                            asm volatile(
                                "ldmatrix.sync.aligned.m8n8.x4.shared.b16 {%0,%1,%2,%3}, [%4];"
                                : "=r"(b_lo[h][0]), "=r"(b_lo[h][1]), "=r"(b_lo[h][2]), "=r"(b_lo[h][3])
                                : "r"(addr_l));
                        }
                        #pragma unroll
                        for (int a1 = 0; a1 < 2; a1++) {
                            #pragma unroll
                            for (int a2 = 0; a2 < 4; a2++) {
                                int h = a2 >> 1, lo = a2 & 1;
                                float* c = acc[d][a1][a2];
                                asm volatile(
                                    "mma.sync.aligned.m16n8k16.row.col.f32.f16.f16.f32 "
                                    "{%0,%1,%2,%3}, {%4,%5,%6,%7}, {%8,%9}, {%0,%1,%2,%3};"
                                    : "+f"(c[0]), "+f"(c[1]), "+f"(c[2]), "+f"(c[3])
                                    : "r"(a_hi[a1][0]), "r"(a_hi[a1][1]), "r"(a_hi[a1][2]), "r"(a_hi[a1][3]),
                                      "r"(b_hi[h][lo]), "r"(b_hi[h][lo + 2]));
                                asm volatile(
                                    "mma.sync.aligned.m16n8k16.row.col.f32.f16.f16.f32 "
                                    "{%0,%1,%2,%3}, {%4,%5,%6,%7}, {%8,%9}, {%0,%1,%2,%3};"
                                    : "+f"(c[0]), "+f"(c[1]), "+f"(c[2]), "+f"(c[3])
                                    : "r"(a_lo[a1][0]), "r"(a_lo[a1][1]), "r"(a_lo[a1][2]), "r"(a_lo[a1][3]),
                                      "r"(b_hi[h][lo]), "r"(b_hi[h][lo + 2]));
                                asm volatile(
                                    "mma.sync.aligned.m16n8k16.row.col.f32.f16.f16.f32 "
                                    "{%0,%1,%2,%3}, {%4,%5,%6,%7}, {%8,%9}, {%0,%1,%2,%3};"
                                    : "+f"(c[0]), "+f"(c[1]), "+f"(c[2]), "+f"(c[3])
                                    : "r"(a_hi[a1][0]), "r"(a_hi[a1][1]), "r"(a_hi[a1][2]), "r"(a_hi[a1][3]),
                                      "r"(b_lo[h][lo]), "r"(b_lo[h][lo + 2]));
                            }
                        }
                    }
                }
                __syncthreads();
                int nk = kt + 2;
                if (nk < NK) load_stage_fb(nk % 3, nk, p);
                CP_COMMIT();
            }
            CP_WAIT(0);
            __syncthreads();

            int g = lane >> 2, t = lane & 3;
            #pragma unroll
            for (int a1 = 0; a1 < 2; a1++) {
                #pragma unroll
                for (int a2 = 0; a2 < 4; a2++) {
                    int row = m0 + 32 * wid + 16 * a1 + g;
                    int col = n0 + 32 * p + 8 * a2 + 2 * t;
                    float p0 = acc[0][a1][a2][0] * acc[1][a1][a2][0] * acc[2][a1][a2][0] * scale;
                    float p1 = acc[0][a1][a2][1] * acc[1][a1][a2][1] * acc[2][a1][a2][1] * scale;
                    float p2 = acc[0][a1][a2][2] * acc[1][a1][a2][2] * acc[2][a1][a2][2] * scale;
                    float p3 = acc[0][a1][a2][3] * acc[1][a1][a2][3] * acc[2][a1][a2][3] * scale;
                    *reinterpret_cast<float2*>(out + (size_t)row * DFEAT + col) =
                        make_float2(p0, p1);
                    *reinterpret_cast<float2*>(out + (size_t)(row + 8) * DFEAT + col) =
                        make_float2(p2, p3);
                }
            }
        }
    }
#endif
}

// ============================================================================
// Launch: encode tensormaps via driver entry point (no -lcuda link needed)
// ============================================================================
typedef CUresult (*PFN_EncodeTiled)(
    CUtensorMap*, CUtensorMapDataType, cuuint32_t, void*,
    const cuuint64_t*, const cuuint64_t*, const cuuint32_t*, const cuuint32_t*,
    CUtensorMapInterleave, CUtensorMapSwizzle, CUtensorMapL2promotion,
    CUtensorMapFloatOOBfill);

extern "C" void kernel_launch(void* const* d_in, const int* in_sizes, int n_in,
                              void* d_out, int out_size) {
    const float* x   = (const float*)d_in[0];
    const float* W   = (const float*)d_in[1];
    const float* lls = (const float*)d_in[2];
    const float* lv  = (const float*)d_in[3];
    float* out = (float*)d_out;

    convert_x_kernel<<<(BATCH * (size_t)DIN) / (4 * 256), 256>>>(x, lls);
    convert_w_kernel<<<dim3(DFEAT / 32, DIN / 32, DEG), dim3(32, 32)>>>(W);
    scale_kernel<<<1, 1>>>(lv);

    PFN_EncodeTiled encode = nullptr;
    cudaDriverEntryPointQueryResult qr;
    cudaGetDriverEntryPoint("cuTensorMapEncodeTiled", (void**)&encode,
                            cudaEnableDefault, &qr);

    void *p_xc = nullptr, *p_wc = nullptr;
    cudaGetSymbolAddress(&p_xc, g_xc);
    cudaGetSymbolAddress(&p_wc, g_wc);

    CUtensorMap map_x{}, map_w{};
    {
        cuuint64_t dims[3]    = {64, NK, BATCH};
        cuuint64_t strides[2] = {128, 128ull * NK};
        cuuint32_t box[3]     = {64, 1, 128};          // A half: 128 rows
        cuuint32_t es[3]      = {1, 1, 1};
        encode(&map_x, CU_TENSOR_MAP_DATA_TYPE_FLOAT16, 3, p_xc,
               dims, strides, box, es,
               CU_TENSOR_MAP_INTERLEAVE_NONE, CU_TENSOR_MAP_SWIZZLE_128B,
               CU_TENSOR_MAP_L2_PROMOTION_L2_128B,
               CU_TENSOR_MAP_FLOAT_OOB_FILL_NONE);
    }
    {
        cuuint64_t dims[3]    = {64, NK, (cuuint64_t)DEG * DFEAT};
        cuuint64_t strides[2] = {128, 128ull * NK};
        cuuint32_t box[3]     = {64, 1, 64};           // B half: 64 rows
        cuuint32_t es[3]      = {1, 1, 1};
        encode(&map_w, CU_TENSOR_MAP_DATA_TYPE_FLOAT16, 3, p_wc,
               dims, strides, box, es,
               CU_TENSOR_MAP_INTERLEAVE_NONE, CU_TENSOR_MAP_SWIZZLE_128B,
               CU_TENSOR_MAP_L2_PROMOTION_L2_128B,
               CU_TENSOR_MAP_FLOAT_OOB_FILL_NONE);
    }

    cudaFuncSetAttribute(sketch_kernel,
                         cudaFuncAttributeMaxDynamicSharedMemorySize, SMEM_TOTAL);
    // 148 persistent CTAs = 74 clusters of 2
    sketch_kernel<<<GRID_CTAS, 128, SMEM_TOTAL>>>(out, map_x, map_w);
}